// round 12
// baseline (speedup 1.0000x reference)
#include <cuda_runtime.h>
#include <cuda_bf16.h>
#include <mma.h>
#include <cstdint>
#include <cstddef>

using namespace nvcuda;

#define BB   2
#define LL   512
#define HIN  1024
#define ENT  16
#define DD   50
#define TOT  850
#define PADN 896
#define NMASK 511
#define SCALE 0.14142135623730951f

// ---------------------------------------------------------------------------
// Scratch (device globals)
// ---------------------------------------------------------------------------
__device__ __nv_bfloat16 g_Xh[1024 * 1024];
__device__ __nv_bfloat16 g_Xl[1024 * 1024];
__device__ __nv_bfloat16 g_WhT[2 * PADN * HIN];   // [z][n][k]
__device__ __nv_bfloat16 g_WlT[2 * PADN * HIN];
__device__ float g_proj_s[BB * (ENT + 1) * LL * DD];
__device__ float g_proj_e[BB * (ENT + 1) * LL * DD];
__device__ float g_conj_s[BB * LL * DD];          // e=16 slice (fp32 path)
__device__ float g_conj_e[BB * LL * DD];
__device__ float g_cd[BB * NMASK];
__device__ float g_fm[BB][LL * LL];               // final_mask (2MB)
__device__ float g_tcos[LL * (DD / 2)];
__device__ float g_tsin[LL * (DD / 2)];
// roped q/k, bf16 hi/lo, [b][e][i][64] (d padded 50->64 with zeros)
__device__ __nv_bfloat16 g_qh[BB * ENT * LL * 64];
__device__ __nv_bfloat16 g_ql[BB * ENT * LL * 64];
__device__ __nv_bfloat16 g_kh[BB * ENT * LL * 64];
__device__ __nv_bfloat16 g_kl[BB * ENT * LL * 64];

// ---------------------------------------------------------------------------
// Prep kernels
// ---------------------------------------------------------------------------
__global__ void split_x(const float* __restrict__ X)
{
    int idx = blockIdx.x * blockDim.x + threadIdx.x;
    if (idx >= 1024 * 1024) return;
    float x = X[idx];
    __nv_bfloat16 h = __float2bfloat16(x);
    __nv_bfloat16 l = __float2bfloat16(x - __bfloat162float(h));
    g_Xh[idx] = h;
    g_Xl[idx] = l;
}

__global__ void split_wT(const float* __restrict__ W0, const float* __restrict__ W1)
{
    __shared__ __nv_bfloat16 th[32][33];
    __shared__ __nv_bfloat16 tl[32][33];
    const int z = blockIdx.z;
    const float* W = z ? W1 : W0;
    const int n0 = blockIdx.x * 32;
    const int k0 = blockIdx.y * 32;
    const int tx = threadIdx.x, ty = threadIdx.y;

    int n = n0 + tx, k = k0 + ty;
    float x = (n < TOT) ? W[(size_t)k * TOT + n] : 0.f;
    __nv_bfloat16 h = __float2bfloat16(x);
    __nv_bfloat16 l = __float2bfloat16(x - __bfloat162float(h));
    th[ty][tx] = h;
    tl[ty][tx] = l;
    __syncthreads();

    int on = n0 + ty, ok = k0 + tx;
    size_t oidx = (size_t)z * PADN * HIN + (size_t)on * HIN + ok;
    g_WhT[oidx] = th[tx][ty];
    g_WlT[oidx] = tl[tx][ty];
}

__global__ void trig_table()
{
    int idx = blockIdx.x * blockDim.x + threadIdx.x;
    if (idx >= LL * (DD / 2)) return;
    int l = idx / (DD / 2), t = idx - l * (DD / 2);
    double inv = exp(-((2.0 * t) / (double)DD) * log(10000.0));
    double ang = (double)l * inv;
    g_tcos[idx] = (float)cos(ang);
    g_tsin[idx] = (float)sin(ang);
}

// ---------------------------------------------------------------------------
// tiny_proj: e=16 columns only (cols 800..849), fp32 SIMT, reads raw W.
// grid (128 m-tiles of 8 rows, 2 z), 128 threads.  (R4-fixed version)
// ---------------------------------------------------------------------------
__global__ __launch_bounds__(128) void tiny_proj(
    const float* __restrict__ X,
    const float* __restrict__ W0, const float* __restrict__ bias0,
    const float* __restrict__ W1, const float* __restrict__ bias1)
{
    const int z = blockIdx.y;
    const int m0 = blockIdx.x * 8;
    const float* W    = z ? W1 : W0;
    const float* bias = z ? bias1 : bias0;
    float* dst        = z ? g_conj_e : g_conj_s;

    __shared__ float Xt[32][8];
    __shared__ float Wt[32][64];    // cols 50..63 zero

    const int tid = threadIdx.x;
    const int r  = tid >> 4;
    const int cg = tid & 15;

    float acc0 = 0.f, acc1 = 0.f, acc2 = 0.f, acc3 = 0.f;

    for (int kc = 0; kc < HIN; kc += 32) {
        if (tid < 64) {
            int row = tid >> 3;
            int ks  = (tid & 7) * 4;
            float4 v = *reinterpret_cast<const float4*>(
                X + (size_t)(m0 + row) * HIN + kc + ks);
            Xt[ks + 0][row] = v.x; Xt[ks + 1][row] = v.y;
            Xt[ks + 2][row] = v.z; Xt[ks + 3][row] = v.w;
        }
        for (int x = tid; x < 32 * 64; x += 128) {
            int kk = x >> 6, d = x & 63;
            Wt[kk][d] = (d < DD) ? W[(size_t)(kc + kk) * TOT + 800 + d] : 0.f;
        }
        __syncthreads();
        #pragma unroll
        for (int kk = 0; kk < 32; kk++) {
            float xv = Xt[kk][r];
            float4 w = *reinterpret_cast<const float4*>(&Wt[kk][cg * 4]);
            acc0 = fmaf(xv, w.x, acc0);
            acc1 = fmaf(xv, w.y, acc1);
            acc2 = fmaf(xv, w.z, acc2);
            acc3 = fmaf(xv, w.w, acc3);
        }
        __syncthreads();
    }
    const float a[4] = {acc0, acc1, acc2, acc3};
    #pragma unroll
    for (int i = 0; i < 4; i++) {
        int d = cg * 4 + i;
        if (d < DD)
            dst[(size_t)(m0 + r) * DD + d] = a[i] + bias[800 + d];
    }
}

// ---------------------------------------------------------------------------
// conj_diag — warp per (b,i), shfl reduce, reads g_conj buffers
// ---------------------------------------------------------------------------
__global__ __launch_bounds__(256) void conj_kernel()
{
    int wg = blockIdx.x * 8 + (threadIdx.x >> 5);
    int lane = threadIdx.x & 31;
    if (wg >= BB * NMASK) return;
    int b = wg / NMASK, i = wg - b * NMASK;
    const float* a = g_conj_s + ((size_t)b * LL + i) * DD;
    const float* c = g_conj_e + ((size_t)b * LL + i + 1) * DD;
    float s = 0.f;
    if (lane < DD)      s  = a[lane] * c[lane];
    if (lane + 32 < DD) s += a[lane + 32] * c[lane + 32];
    #pragma unroll
    for (int o = 16; o > 0; o >>= 1)
        s += __shfl_xor_sync(0xFFFFFFFFu, s, o);
    if (lane == 0) g_cd[wg] = s * SCALE;
}

// ---------------------------------------------------------------------------
// mask_kernel — R1 mask phase shape (measured-fast), writes g_fm.
// ---------------------------------------------------------------------------
__global__ __launch_bounds__(256) void mask_kernel(const float* __restrict__ mask)
{
    __shared__ float scd[BB * NMASK];
    const int tid = threadIdx.x;
    const int tx = tid & 15, ty = tid >> 4;

    for (int k = tid; k < BB * NMASK; k += 256) scd[k] = g_cd[k];

    const int i0 = blockIdx.y * 16, j0 = blockIdx.x * 16;
    const int i = i0 + ty, j = j0 + tx;
    const float* mp = mask + (size_t)i * LL + j;

    __syncthreads();

    float a0 = 0.f, a1 = 0.f;
    int k = 0;
    for (; k + 8 <= NMASK; k += 8) {
        float m[8];
        #pragma unroll
        for (int u = 0; u < 8; u++) m[u] = mp[(size_t)(k + u) * (LL * LL)];
        #pragma unroll
        for (int u = 0; u < 8; u++) {
            a0 = fmaf(scd[k + u],          m[u], a0);
            a1 = fmaf(scd[NMASK + k + u],  m[u], a1);
        }
    }
    for (; k < NMASK; k++) {
        float m = mp[(size_t)k * (LL * LL)];
        a0 = fmaf(scd[k],         m, a0);
        a1 = fmaf(scd[NMASK + k], m, a1);
    }

    g_fm[0][(size_t)i * LL + j] = a0;
    g_fm[1][(size_t)i * LL + j] = a1;
}

// ---------------------------------------------------------------------------
// WMMA bf16 GEMM (R8 128x64 config) + RoPE fused; writes e<16 only.
// ---------------------------------------------------------------------------
union GemmSmem {
    struct {
        __nv_bfloat16 Ah[128][40];
        __nv_bfloat16 Al[128][40];
        __nv_bfloat16 Bh[64][40];
        __nv_bfloat16 Bl[64][40];
    } t;
    float out[128][68];
};

__global__ __launch_bounds__(256) void gemm_wmma(
    const float* __restrict__ bias0, const float* __restrict__ bias1)
{
    __shared__ GemmSmem sm;

    const int z  = blockIdx.z;
    const int n0 = blockIdx.x * 64;
    const int m0 = blockIdx.y * 128;
    const float* bias = z ? bias1 : bias0;
    float* dst        = z ? g_proj_e : g_proj_s;

    const int tid = threadIdx.x;
    const int wid = tid >> 5;
    const int wr = wid >> 1;
    const int wc = wid & 1;

    const uint4* Xh4 = reinterpret_cast<const uint4*>(g_Xh);
    const uint4* Xl4 = reinterpret_cast<const uint4*>(g_Xl);
    const uint4* Bh4 = reinterpret_cast<const uint4*>(g_WhT) + (size_t)z * PADN * 128;
    const uint4* Bl4 = reinterpret_cast<const uint4*>(g_WlT) + (size_t)z * PADN * 128;

    wmma::fragment<wmma::accumulator, 16, 16, 16, float> c[2][2];
    #pragma unroll
    for (int i = 0; i < 2; i++)
        #pragma unroll
        for (int j = 0; j < 2; j++)
            wmma::fill_fragment(c[i][j], 0.f);

    for (int kc = 0; kc < HIN; kc += 32) {
        const int kc8 = kc >> 3;
        #pragma unroll
        for (int it = 0; it < 2; it++) {
            int u = it * 256 + tid;
            int row = u >> 2, c8 = u & 3;
            size_t gi = (size_t)(m0 + row) * 128 + kc8 + c8;
            *reinterpret_cast<uint4*>(&sm.t.Ah[row][c8 * 8]) = Xh4[gi];
            *reinterpret_cast<uint4*>(&sm.t.Al[row][c8 * 8]) = Xl4[gi];
        }
        {
            int row = tid >> 2, c8 = tid & 3;
            size_t gi = (size_t)(n0 + row) * 128 + kc8 + c8;
            *reinterpret_cast<uint4*>(&sm.t.Bh[row][c8 * 8]) = Bh4[gi];
            *reinterpret_cast<uint4*>(&sm.t.Bl[row][c8 * 8]) = Bl4[gi];
        }
        __syncthreads();

        #pragma unroll
        for (int ks = 0; ks < 32; ks += 16) {
            wmma::fragment<wmma::matrix_a, 16, 16, 16, __nv_bfloat16, wmma::row_major> ah[2], al[2];
            wmma::fragment<wmma::matrix_b, 16, 16, 16, __nv_bfloat16, wmma::col_major> bh[2], bl[2];
            #pragma unroll
            for (int i = 0; i < 2; i++) {
                wmma::load_matrix_sync(ah[i], &sm.t.Ah[wr * 32 + i * 16][ks], 40);
                wmma::load_matrix_sync(al[i], &sm.t.Al[wr * 32 + i * 16][ks], 40);
            }
            #pragma unroll
            for (int j = 0; j < 2; j++) {
                wmma::load_matrix_sync(bh[j], &sm.t.Bh[wc * 32 + j * 16][ks], 40);
                wmma::load_matrix_sync(bl[j], &sm.t.Bl[wc * 32 + j * 16][ks], 40);
            }
            #pragma unroll
            for (int i = 0; i < 2; i++)
                #pragma unroll
                for (int j = 0; j < 2; j++) {
                    wmma::mma_sync(c[i][j], ah[i], bh[j], c[i][j]);
                    wmma::mma_sync(c[i][j], ah[i], bl[j], c[i][j]);
                    wmma::mma_sync(c[i][j], al[i], bh[j], c[i][j]);
                }
        }
        __syncthreads();
    }

    #pragma unroll
    for (int i = 0; i < 2; i++)
        #pragma unroll
        for (int j = 0; j < 2; j++)
            wmma::store_matrix_sync(&sm.out[wr * 32 + i * 16][wc * 32 + j * 16],
                                    c[i][j], 68, wmma::mem_row_major);
    __syncthreads();

    // Epilogue with fused RoPE; e=16 (cols >= 800) handled by tiny_proj.
    for (int idx = tid; idx < 128 * 32; idx += 256) {
        int row = idx >> 5, cp = idx & 31;
        int n = n0 + cp * 2;
        if (n < 800) {
            int e = n / DD, d = n - e * DD;
            int m = m0 + row;
            int b = m >> 9, l = m & 511;
            float v0 = sm.out[row][cp * 2]     + bias[n];
            float v1 = sm.out[row][cp * 2 + 1] + bias[n + 1];
            int t = d >> 1;
            float cc = g_tcos[l * (DD / 2) + t];
            float ss = g_tsin[l * (DD / 2) + t];
            float r0 = v0 * cc - v1 * ss;
            float r1 = v1 * cc + v0 * ss;
            size_t o = (((size_t)b * (ENT + 1) + e) * LL + l) * DD + d;
            dst[o]     = r0;
            dst[o + 1] = r1;
        }
    }
}

// ---------------------------------------------------------------------------
// split_qk: roped fp32 q/k (e<16) -> bf16 hi/lo, [b][e][i][64], zero-pad d
// ---------------------------------------------------------------------------
__global__ void split_qk()
{
    int idx = blockIdx.x * blockDim.x + threadIdx.x;
    const int total = BB * ENT * LL * 64;
    if (idx >= total) return;
    int d = idx & 63;
    int r = idx >> 6;
    int i = r & 511;  r >>= 9;
    int e = r & 15;   int b = r >> 4;

    float q = 0.f, k = 0.f;
    if (d < DD) {
        size_t src = (((size_t)b * (ENT + 1) + e) * LL + i) * DD + d;
        q = g_proj_s[src];
        k = g_proj_e[src];
    }
    __nv_bfloat16 qh = __float2bfloat16(q);
    __nv_bfloat16 kh = __float2bfloat16(k);
    g_qh[idx] = qh;
    g_ql[idx] = __float2bfloat16(q - __bfloat162float(qh));
    g_kh[idx] = kh;
    g_kl[idx] = __float2bfloat16(k - __bfloat162float(kh));
}

// ---------------------------------------------------------------------------
// scores_wmma (R11, measured-good): (b, 32i x 32j) per block, split-bf16 WMMA.
// ---------------------------------------------------------------------------
#define SS_LD   36
#define TILE_LD 72
#define SMEM_SS_BYTES   (16 * 32 * SS_LD * 4)
#define SMEM_TILE_BYTES (8 * 32 * TILE_LD * 2)
#define SCORES_SMEM     (SMEM_SS_BYTES + SMEM_TILE_BYTES)

__global__ __launch_bounds__(256) void scores_wmma(float* __restrict__ out)
{
    extern __shared__ char smem[];
    float* sS = reinterpret_cast<float*>(smem);
    __nv_bfloat16* tiles = reinterpret_cast<__nv_bfloat16*>(smem + SMEM_SS_BYTES);

    const int tid = threadIdx.x;
    const int wid = tid >> 5;
    const int j0 = blockIdx.x * 32;
    const int i0 = blockIdx.y * 32;
    const int b  = blockIdx.z;

    const uint4* qh4 = reinterpret_cast<const uint4*>(g_qh);
    const uint4* ql4 = reinterpret_cast<const uint4*>(g_ql);
    const uint4* kh4 = reinterpret_cast<const uint4*>(g_kh);
    const uint4* kl4 = reinterpret_cast<const uint4*>(g_kl);

    for (int ep = 0; ep < 8; ep++) {
        const int e0 = ep * 2;
        __syncthreads();
        #pragma unroll
        for (int it = 0; it < 8; it++) {
            int g = it * 256 + tid;
            int c   = g & 7;
            int r   = (g >> 3) & 31;
            int mat = g >> 8;
            int hl = mat & 1, el = (mat >> 1) & 1, qk = mat >> 2;
            const uint4* src = qk ? (hl ? kl4 : kh4) : (hl ? ql4 : qh4);
            int row0 = qk ? j0 : i0;
            size_t gi = ((size_t)(b * ENT + e0 + el) * LL + row0 + r) * 8 + c;
            uint4 v = src[gi];
            *reinterpret_cast<uint4*>(
                &tiles[((qk * 4 + el * 2 + hl) * 32 + r) * TILE_LD + c * 8]) = v;
        }
        __syncthreads();

        const int el  = wid >> 2;
        const int qi  = ((wid >> 1) & 1) * 16;
        const int qj  = (wid & 1) * 16;
        const __nv_bfloat16* Qh_ = &tiles[((el * 2 + 0) * 32 + qi) * TILE_LD];
        const __nv_bfloat16* Ql_ = &tiles[((el * 2 + 1) * 32 + qi) * TILE_LD];
        const __nv_bfloat16* Kh_ = &tiles[((4 + el * 2 + 0) * 32 + qj) * TILE_LD];
        const __nv_bfloat16* Kl_ = &tiles[((4 + el * 2 + 1) * 32 + qj) * TILE_LD];

        wmma::fragment<wmma::accumulator, 16, 16, 16, float> acc;
        wmma::fill_fragment(acc, 0.f);
        #pragma unroll
        for (int ks = 0; ks < 64; ks += 16) {
            wmma::fragment<wmma::matrix_a, 16, 16, 16, __nv_bfloat16, wmma::row_major> ah, al;
            wmma::fragment<wmma::matrix_b, 16, 16, 16, __nv_bfloat16, wmma::col_major> bh, bl;
            wmma::load_matrix_sync(ah, Qh_ + ks, TILE_LD);
            wmma::load_matrix_sync(al, Ql_ + ks, TILE_LD);
            wmma::load_matrix_sync(bh, Kh_ + ks, TILE_LD);
            wmma::load_matrix_sync(bl, Kl_ + ks, TILE_LD);
            wmma::mma_sync(acc, ah, bh, acc);
            wmma::mma_sync(acc, ah, bl, acc);
            wmma::mma_sync(acc, al, bh, acc);
        }
        wmma::store_matrix_sync(&sS[(e0 + el) * 32 * SS_LD + qi * SS_LD + qj],
                                acc, SS_LD, wmma::mem_row_major);
    }
    __syncthreads();

    for (int v = 0; v < 4; v++) {
        int lin = v * 256 + tid;
        int jj = lin & 31, ii = lin >> 5;
        int i = i0 + ii, j = j0 + jj;
        float fm = g_fm[b][(size_t)i * LL + j];
        float* op = out + ((((size_t)b * LL + i) * LL + j) * ENT);
        const float* sp = &sS[ii * SS_LD + jj];
        #pragma unroll
        for (int q = 0; q < 4; q++) {
            float4 w;
            w.x = fmaf(sp[(4 * q + 0) * 32 * SS_LD], SCALE, fm);
            w.y = fmaf(sp[(4 * q + 1) * 32 * SS_LD], SCALE, fm);
            w.z = fmaf(sp[(4 * q + 2) * 32 * SS_LD], SCALE, fm);
            w.w = fmaf(sp[(4 * q + 3) * 32 * SS_LD], SCALE, fm);
            *reinterpret_cast<float4*>(op + 4 * q) = w;
        }
    }
}

// ---------------------------------------------------------------------------
extern "C" void kernel_launch(void* const* d_in, const int* in_sizes, int n_in,
                              void* d_out, int out_size)
{
    const float* X    = (const float*)d_in[0];
    const float* mask = (const float*)d_in[1];
    const float* Ws   = (const float*)d_in[2];
    const float* bs   = (const float*)d_in[3];
    const float* We   = (const float*)d_in[4];
    const float* be   = (const float*)d_in[5];
    float* out        = (float*)d_out;

    static cudaStream_t s2 = nullptr;
    static cudaEvent_t evFork = nullptr, evJoin = nullptr;
    if (!s2) {
        cudaStreamCreateWithFlags(&s2, cudaStreamNonBlocking);
        cudaEventCreateWithFlags(&evFork, cudaEventDisableTiming);
        cudaEventCreateWithFlags(&evJoin, cudaEventDisableTiming);
        cudaFuncSetAttribute(scores_wmma,
            cudaFuncAttributeMaxDynamicSharedMemorySize, SCORES_SMEM);
    }

    // Fork: stream B computes conj-diag chain + the DRAM-bound mask stream
    // while the default stream runs the L1/tensor-bound projection GEMM.
    cudaEventRecord(evFork, 0);
    cudaStreamWaitEvent(s2, evFork, 0);

    // --- stream B (DRAM-bound branch) ---
    tiny_proj<<<dim3(LL * BB / 8, 2), 128, 0, s2>>>(X, Ws, bs, We, be);
    conj_kernel<<<(BB * NMASK + 7) / 8, 256, 0, s2>>>();
    mask_kernel<<<dim3(LL / 16, LL / 16), 256, 0, s2>>>(mask);
    cudaEventRecord(evJoin, s2);

    // --- default stream (compute-bound branch) ---
    split_x<<<(1024 * 1024 + 255) / 256, 256>>>(X);
    split_wT<<<dim3(PADN / 32, HIN / 32, 2), dim3(32, 32)>>>(Ws, We);
    trig_table<<<(LL * (DD / 2) + 255) / 256, 256>>>();
    gemm_wmma<<<dim3(PADN / 64, 1024 / 128, 2), 256>>>(bs, be);
    split_qk<<<(BB * ENT * LL * 64 + 255) / 256, 256>>>();

    // Join, then final scores
    cudaStreamWaitEvent(0, evJoin, 0);
    scores_wmma<<<dim3(LL / 32, LL / 32, 2), 256, SCORES_SMEM>>>(out);
}

// round 13
// speedup vs baseline: 1.0980x; 1.0980x over previous
#include <cuda_runtime.h>
#include <cuda_bf16.h>
#include <mma.h>
#include <cstdint>
#include <cstddef>

using namespace nvcuda;

#define BB   2
#define LL   512
#define HIN  1024
#define ENT  16
#define DD   50
#define TOT  850
#define PADN 896
#define NMASK 511
#define SCALE 0.14142135623730951f

// ---------------------------------------------------------------------------
// Scratch (device globals)
// ---------------------------------------------------------------------------
__device__ __nv_bfloat16 g_Xh[1024 * 1024];
__device__ __nv_bfloat16 g_Xl[1024 * 1024];
__device__ __nv_bfloat16 g_WhT[2 * PADN * HIN];   // [z][n][k]
__device__ __nv_bfloat16 g_WlT[2 * PADN * HIN];
__device__ float g_proj_s[BB * (ENT + 1) * LL * DD];
__device__ float g_proj_e[BB * (ENT + 1) * LL * DD];
__device__ float g_cd[BB * NMASK];
__device__ float g_fm[BB][LL * LL];               // final_mask (2MB)
__device__ float g_tcos[LL * (DD / 2)];
__device__ float g_tsin[LL * (DD / 2)];
// roped q/k, bf16 hi/lo, [b][e][i][64] (d padded 50->64 with zeros)
__device__ __nv_bfloat16 g_qh[BB * ENT * LL * 64];
__device__ __nv_bfloat16 g_ql[BB * ENT * LL * 64];
__device__ __nv_bfloat16 g_kh[BB * ENT * LL * 64];
__device__ __nv_bfloat16 g_kl[BB * ENT * LL * 64];

// ---------------------------------------------------------------------------
// cp.async helpers (sm_80+ portable PTX)
// ---------------------------------------------------------------------------
__device__ __forceinline__ void cp_async16(void* s, const void* g)
{
    uint32_t sa = (uint32_t)__cvta_generic_to_shared(s);
    asm volatile("cp.async.ca.shared.global [%0], [%1], 16;"
                 :: "r"(sa), "l"(g) : "memory");
}
#define CP_COMMIT() asm volatile("cp.async.commit_group;" ::: "memory")
#define CP_WAIT(n)  asm volatile("cp.async.wait_group %0;" :: "n"(n) : "memory")

// ---------------------------------------------------------------------------
// Prep kernels
// ---------------------------------------------------------------------------
__global__ void split_x(const float* __restrict__ X)
{
    int idx = blockIdx.x * blockDim.x + threadIdx.x;
    if (idx >= 1024 * 1024) return;
    float x = X[idx];
    __nv_bfloat16 h = __float2bfloat16(x);
    __nv_bfloat16 l = __float2bfloat16(x - __bfloat162float(h));
    g_Xh[idx] = h;
    g_Xl[idx] = l;
}

__global__ void split_wT(const float* __restrict__ W0, const float* __restrict__ W1)
{
    __shared__ __nv_bfloat16 th[32][33];
    __shared__ __nv_bfloat16 tl[32][33];
    const int z = blockIdx.z;
    const float* W = z ? W1 : W0;
    const int n0 = blockIdx.x * 32;
    const int k0 = blockIdx.y * 32;
    const int tx = threadIdx.x, ty = threadIdx.y;

    int n = n0 + tx, k = k0 + ty;
    float x = (n < TOT) ? W[(size_t)k * TOT + n] : 0.f;
    __nv_bfloat16 h = __float2bfloat16(x);
    __nv_bfloat16 l = __float2bfloat16(x - __bfloat162float(h));
    th[ty][tx] = h;
    tl[ty][tx] = l;
    __syncthreads();

    int on = n0 + ty, ok = k0 + tx;
    size_t oidx = (size_t)z * PADN * HIN + (size_t)on * HIN + ok;
    g_WhT[oidx] = th[tx][ty];
    g_WlT[oidx] = tl[tx][ty];
}

__global__ void trig_table()
{
    int idx = blockIdx.x * blockDim.x + threadIdx.x;
    if (idx >= LL * (DD / 2)) return;
    int l = idx / (DD / 2), t = idx - l * (DD / 2);
    double inv = exp(-((2.0 * t) / (double)DD) * log(10000.0));
    double ang = (double)l * inv;
    g_tcos[idx] = (float)cos(ang);
    g_tsin[idx] = (float)sin(ang);
}

// ---------------------------------------------------------------------------
// WMMA bf16 GEMM + fused RoPE, 2-stage cp.async pipeline.
// Tile M128 x N64, K staged 32, grid (14, 8, 2), 256 threads.
// ---------------------------------------------------------------------------
struct GemmSmemP {
    union {
        struct {
            __nv_bfloat16 Ah[2][128][40];
            __nv_bfloat16 Al[2][128][40];
            __nv_bfloat16 Bh[2][64][40];
            __nv_bfloat16 Bl[2][64][40];
        } t;                       // 61440 B
        float out[128][68];        // 34816 B
    } u;
};
#define GEMM_SMEM sizeof(GemmSmemP)

__device__ __forceinline__ void gemm_prefetch(
    GemmSmemP* sm, int st, int kc, int m0, int n0, int tid,
    const uint4* Xh4, const uint4* Xl4, const uint4* Bh4, const uint4* Bl4)
{
    const int kc4 = kc * 4;        // 32 bf16 = 4 uint4 per row-chunk
    #pragma unroll
    for (int it = 0; it < 6; it++) {
        int g = it * 256 + tid;    // 0..1535
        if (g < 512) {
            int row = g >> 2, c8 = g & 3;
            cp_async16(&sm->u.t.Ah[st][row][c8 * 8],
                       Xh4 + (size_t)(m0 + row) * 128 + kc4 + c8);
        } else if (g < 1024) {
            int gg = g - 512; int row = gg >> 2, c8 = gg & 3;
            cp_async16(&sm->u.t.Al[st][row][c8 * 8],
                       Xl4 + (size_t)(m0 + row) * 128 + kc4 + c8);
        } else if (g < 1280) {
            int gg = g - 1024; int row = gg >> 2, c8 = gg & 3;
            cp_async16(&sm->u.t.Bh[st][row][c8 * 8],
                       Bh4 + (size_t)(n0 + row) * 128 + kc4 + c8);
        } else {
            int gg = g - 1280; int row = gg >> 2, c8 = gg & 3;
            cp_async16(&sm->u.t.Bl[st][row][c8 * 8],
                       Bl4 + (size_t)(n0 + row) * 128 + kc4 + c8);
        }
    }
}

__global__ __launch_bounds__(256) void gemm_wmma(
    const float* __restrict__ bias0, const float* __restrict__ bias1)
{
    extern __shared__ char dyn[];
    GemmSmemP* sm = reinterpret_cast<GemmSmemP*>(dyn);

    const int z  = blockIdx.z;
    const int n0 = blockIdx.x * 64;
    const int m0 = blockIdx.y * 128;
    const float* bias = z ? bias1 : bias0;
    float* dst        = z ? g_proj_e : g_proj_s;

    const int tid = threadIdx.x;
    const int wid = tid >> 5;
    const int wr = wid >> 1;
    const int wc = wid & 1;

    const uint4* Xh4 = reinterpret_cast<const uint4*>(g_Xh);
    const uint4* Xl4 = reinterpret_cast<const uint4*>(g_Xl);
    const uint4* Bh4 = reinterpret_cast<const uint4*>(g_WhT) + (size_t)z * PADN * 128;
    const uint4* Bl4 = reinterpret_cast<const uint4*>(g_WlT) + (size_t)z * PADN * 128;

    wmma::fragment<wmma::accumulator, 16, 16, 16, float> c[2][2];
    #pragma unroll
    for (int i = 0; i < 2; i++)
        #pragma unroll
        for (int j = 0; j < 2; j++)
            wmma::fill_fragment(c[i][j], 0.f);

    gemm_prefetch(sm, 0, 0, m0, n0, tid, Xh4, Xl4, Bh4, Bl4);
    CP_COMMIT();

    for (int kc = 0; kc < 32; kc++) {
        const int cur = kc & 1;
        if (kc + 1 < 32) {
            gemm_prefetch(sm, cur ^ 1, kc + 1, m0, n0, tid, Xh4, Xl4, Bh4, Bl4);
            CP_COMMIT();
            CP_WAIT(1);            // chunk kc resident; kc+1 in flight
        } else {
            CP_WAIT(0);
        }
        __syncthreads();

        #pragma unroll
        for (int ks = 0; ks < 32; ks += 16) {
            wmma::fragment<wmma::matrix_a, 16, 16, 16, __nv_bfloat16, wmma::row_major> ah[2], al[2];
            wmma::fragment<wmma::matrix_b, 16, 16, 16, __nv_bfloat16, wmma::col_major> bh[2], bl[2];
            #pragma unroll
            for (int i = 0; i < 2; i++) {
                wmma::load_matrix_sync(ah[i], &sm->u.t.Ah[cur][wr * 32 + i * 16][ks], 40);
                wmma::load_matrix_sync(al[i], &sm->u.t.Al[cur][wr * 32 + i * 16][ks], 40);
            }
            #pragma unroll
            for (int j = 0; j < 2; j++) {
                wmma::load_matrix_sync(bh[j], &sm->u.t.Bh[cur][wc * 32 + j * 16][ks], 40);
                wmma::load_matrix_sync(bl[j], &sm->u.t.Bl[cur][wc * 32 + j * 16][ks], 40);
            }
            #pragma unroll
            for (int i = 0; i < 2; i++)
                #pragma unroll
                for (int j = 0; j < 2; j++) {
                    wmma::mma_sync(c[i][j], ah[i], bh[j], c[i][j]);
                    wmma::mma_sync(c[i][j], ah[i], bl[j], c[i][j]);
                    wmma::mma_sync(c[i][j], al[i], bh[j], c[i][j]);
                }
        }
        __syncthreads();          // protect stage cur before kc+2 prefetch
    }

    #pragma unroll
    for (int i = 0; i < 2; i++)
        #pragma unroll
        for (int j = 0; j < 2; j++)
            wmma::store_matrix_sync(&sm->u.out[wr * 32 + i * 16][wc * 32 + j * 16],
                                    c[i][j], 68, wmma::mem_row_major);
    __syncthreads();

    // Epilogue with fused RoPE (even/odd pair per thread; DD even)
    for (int idx = tid; idx < 128 * 32; idx += 256) {
        int row = idx >> 5, cp = idx & 31;
        int n = n0 + cp * 2;
        if (n < TOT) {
            int e = n / DD, d = n - e * DD;
            int m = m0 + row;
            int b = m >> 9, l = m & 511;
            float v0 = sm->u.out[row][cp * 2]     + bias[n];
            float v1 = sm->u.out[row][cp * 2 + 1] + bias[n + 1];
            if (e < ENT) {
                int t = d >> 1;
                float cc = g_tcos[l * (DD / 2) + t];
                float ss = g_tsin[l * (DD / 2) + t];
                float r0 = v0 * cc - v1 * ss;
                float r1 = v1 * cc + v0 * ss;
                v0 = r0; v1 = r1;
            }
            size_t o = (((size_t)b * (ENT + 1) + e) * LL + l) * DD + d;
            dst[o]     = v0;
            dst[o + 1] = v1;
        }
    }
}

// ---------------------------------------------------------------------------
// conj_diag — warp per (b,i), shfl reduce (e=16 slice is never roped)
// ---------------------------------------------------------------------------
__global__ __launch_bounds__(256) void conj_kernel()
{
    int wg = blockIdx.x * 8 + (threadIdx.x >> 5);
    int lane = threadIdx.x & 31;
    if (wg >= BB * NMASK) return;
    int b = wg / NMASK, i = wg - b * NMASK;
    const float* a = g_proj_s + (((size_t)b * (ENT + 1) + ENT) * LL + i) * DD;
    const float* c = g_proj_e + (((size_t)b * (ENT + 1) + ENT) * LL + (i + 1)) * DD;
    float s = 0.f;
    if (lane < DD)      s  = a[lane] * c[lane];
    if (lane + 32 < DD) s += a[lane + 32] * c[lane + 32];
    #pragma unroll
    for (int o = 16; o > 0; o >>= 1)
        s += __shfl_xor_sync(0xFFFFFFFFu, s, o);
    if (lane == 0) g_cd[wg] = s * SCALE;
}

// ---------------------------------------------------------------------------
// split_qk: roped fp32 q/k (e<16) -> bf16 hi/lo, [b][e][i][64], zero-pad d
// ---------------------------------------------------------------------------
__global__ void split_qk()
{
    int idx = blockIdx.x * blockDim.x + threadIdx.x;
    const int total = BB * ENT * LL * 64;
    if (idx >= total) return;
    int d = idx & 63;
    int r = idx >> 6;
    int i = r & 511;  r >>= 9;
    int e = r & 15;   int b = r >> 4;

    float q = 0.f, k = 0.f;
    if (d < DD) {
        size_t src = (((size_t)b * (ENT + 1) + e) * LL + i) * DD + d;
        q = g_proj_s[src];
        k = g_proj_e[src];
    }
    __nv_bfloat16 qh = __float2bfloat16(q);
    __nv_bfloat16 kh = __float2bfloat16(k);
    g_qh[idx] = qh;
    g_ql[idx] = __float2bfloat16(q - __bfloat162float(qh));
    g_kh[idx] = kh;
    g_kl[idx] = __float2bfloat16(k - __bfloat162float(kh));
}

// ---------------------------------------------------------------------------
// mask_kernel — R1 shape, unroll raised 8 -> 16 for deeper MLP.
// ---------------------------------------------------------------------------
__global__ __launch_bounds__(256) void mask_kernel(const float* __restrict__ mask)
{
    __shared__ float scd[BB * NMASK];
    const int tid = threadIdx.x;
    const int tx = tid & 15, ty = tid >> 4;

    for (int k = tid; k < BB * NMASK; k += 256) scd[k] = g_cd[k];

    const int i0 = blockIdx.y * 16, j0 = blockIdx.x * 16;
    const int i = i0 + ty, j = j0 + tx;
    const float* mp = mask + (size_t)i * LL + j;

    __syncthreads();

    float a0 = 0.f, a1 = 0.f;
    int k = 0;
    for (; k + 16 <= NMASK; k += 16) {
        float m[16];
        #pragma unroll
        for (int u = 0; u < 16; u++) m[u] = mp[(size_t)(k + u) * (LL * LL)];
        #pragma unroll
        for (int u = 0; u < 16; u++) {
            a0 = fmaf(scd[k + u],          m[u], a0);
            a1 = fmaf(scd[NMASK + k + u],  m[u], a1);
        }
    }
    for (; k < NMASK; k++) {
        float m = mp[(size_t)k * (LL * LL)];
        a0 = fmaf(scd[k],         m, a0);
        a1 = fmaf(scd[NMASK + k], m, a1);
    }

    g_fm[0][(size_t)i * LL + j] = a0;
    g_fm[1][(size_t)i * LL + j] = a1;
}

// ---------------------------------------------------------------------------
// scores_wmma (R11, measured-good): (b, 32i x 32j) per block, split-bf16 WMMA.
// ---------------------------------------------------------------------------
#define SS_LD   36
#define TILE_LD 72
#define SMEM_SS_BYTES   (16 * 32 * SS_LD * 4)
#define SMEM_TILE_BYTES (8 * 32 * TILE_LD * 2)
#define SCORES_SMEM     (SMEM_SS_BYTES + SMEM_TILE_BYTES)

__global__ __launch_bounds__(256) void scores_wmma(float* __restrict__ out)
{
    extern __shared__ char smem[];
    float* sS = reinterpret_cast<float*>(smem);
    __nv_bfloat16* tiles = reinterpret_cast<__nv_bfloat16*>(smem + SMEM_SS_BYTES);

    const int tid = threadIdx.x;
    const int wid = tid >> 5;
    const int j0 = blockIdx.x * 32;
    const int i0 = blockIdx.y * 32;
    const int b  = blockIdx.z;

    const uint4* qh4 = reinterpret_cast<const uint4*>(g_qh);
    const uint4* ql4 = reinterpret_cast<const uint4*>(g_ql);
    const uint4* kh4 = reinterpret_cast<const uint4*>(g_kh);
    const uint4* kl4 = reinterpret_cast<const uint4*>(g_kl);

    for (int ep = 0; ep < 8; ep++) {
        const int e0 = ep * 2;
        __syncthreads();
        #pragma unroll
        for (int it = 0; it < 8; it++) {
            int g = it * 256 + tid;
            int c   = g & 7;
            int r   = (g >> 3) & 31;
            int mat = g >> 8;
            int hl = mat & 1, el = (mat >> 1) & 1, qk = mat >> 2;
            const uint4* src = qk ? (hl ? kl4 : kh4) : (hl ? ql4 : qh4);
            int row0 = qk ? j0 : i0;
            size_t gi = ((size_t)(b * ENT + e0 + el) * LL + row0 + r) * 8 + c;
            uint4 v = src[gi];
            *reinterpret_cast<uint4*>(
                &tiles[((qk * 4 + el * 2 + hl) * 32 + r) * TILE_LD + c * 8]) = v;
        }
        __syncthreads();

        const int el  = wid >> 2;
        const int qi  = ((wid >> 1) & 1) * 16;
        const int qj  = (wid & 1) * 16;
        const __nv_bfloat16* Qh_ = &tiles[((el * 2 + 0) * 32 + qi) * TILE_LD];
        const __nv_bfloat16* Ql_ = &tiles[((el * 2 + 1) * 32 + qi) * TILE_LD];
        const __nv_bfloat16* Kh_ = &tiles[((4 + el * 2 + 0) * 32 + qj) * TILE_LD];
        const __nv_bfloat16* Kl_ = &tiles[((4 + el * 2 + 1) * 32 + qj) * TILE_LD];

        wmma::fragment<wmma::accumulator, 16, 16, 16, float> acc;
        wmma::fill_fragment(acc, 0.f);
        #pragma unroll
        for (int ks = 0; ks < 64; ks += 16) {
            wmma::fragment<wmma::matrix_a, 16, 16, 16, __nv_bfloat16, wmma::row_major> ah, al;
            wmma::fragment<wmma::matrix_b, 16, 16, 16, __nv_bfloat16, wmma::col_major> bh, bl;
            wmma::load_matrix_sync(ah, Qh_ + ks, TILE_LD);
            wmma::load_matrix_sync(al, Ql_ + ks, TILE_LD);
            wmma::load_matrix_sync(bh, Kh_ + ks, TILE_LD);
            wmma::load_matrix_sync(bl, Kl_ + ks, TILE_LD);
            wmma::mma_sync(acc, ah, bh, acc);
            wmma::mma_sync(acc, ah, bl, acc);
            wmma::mma_sync(acc, al, bh, acc);
        }
        wmma::store_matrix_sync(&sS[(e0 + el) * 32 * SS_LD + qi * SS_LD + qj],
                                acc, SS_LD, wmma::mem_row_major);
    }
    __syncthreads();

    for (int v = 0; v < 4; v++) {
        int lin = v * 256 + tid;
        int jj = lin & 31, ii = lin >> 5;
        int i = i0 + ii, j = j0 + jj;
        float fm = g_fm[b][(size_t)i * LL + j];
        float* op = out + ((((size_t)b * LL + i) * LL + j) * ENT);
        const float* sp = &sS[ii * SS_LD + jj];
        #pragma unroll
        for (int q = 0; q < 4; q++) {
            float4 w;
            w.x = fmaf(sp[(4 * q + 0) * 32 * SS_LD], SCALE, fm);
            w.y = fmaf(sp[(4 * q + 1) * 32 * SS_LD], SCALE, fm);
            w.z = fmaf(sp[(4 * q + 2) * 32 * SS_LD], SCALE, fm);
            w.w = fmaf(sp[(4 * q + 3) * 32 * SS_LD], SCALE, fm);
            *reinterpret_cast<float4*>(op + 4 * q) = w;
        }
    }
}

// ---------------------------------------------------------------------------
extern "C" void kernel_launch(void* const* d_in, const int* in_sizes, int n_in,
                              void* d_out, int out_size)
{
    const float* X    = (const float*)d_in[0];
    const float* mask = (const float*)d_in[1];
    const float* Ws   = (const float*)d_in[2];
    const float* bs   = (const float*)d_in[3];
    const float* We   = (const float*)d_in[4];
    const float* be   = (const float*)d_in[5];
    float* out        = (float*)d_out;

    cudaFuncSetAttribute(scores_wmma,
        cudaFuncAttributeMaxDynamicSharedMemorySize, SCORES_SMEM);
    cudaFuncSetAttribute(gemm_wmma,
        cudaFuncAttributeMaxDynamicSharedMemorySize, GEMM_SMEM);

    split_x<<<(1024 * 1024 + 255) / 256, 256>>>(X);
    split_wT<<<dim3(PADN / 32, HIN / 32, 2), dim3(32, 32)>>>(Ws, We);
    trig_table<<<(LL * (DD / 2) + 255) / 256, 256>>>();

    gemm_wmma<<<dim3(PADN / 64, 1024 / 128, 2), 256, GEMM_SMEM>>>(bs, be);

    conj_kernel<<<(BB * NMASK + 7) / 8, 256>>>();
    split_qk<<<(BB * ENT * LL * 64 + 255) / 256, 256>>>();

    mask_kernel<<<dim3(LL / 16, LL / 16), 256>>>(mask);
    scores_wmma<<<dim3(LL / 32, LL / 32, 2), 256, SCORES_SMEM>>>(out);
}

// round 14
// speedup vs baseline: 1.1286x; 1.0279x over previous
#include <cuda_runtime.h>
#include <cuda_bf16.h>
#include <mma.h>
#include <cstdint>
#include <cstddef>

using namespace nvcuda;

#define BB   2
#define LL   512
#define HIN  1024
#define ENT  16
#define DD   50
#define TOT  850
#define PADN 896
#define NMASK 511
#define SCALE 0.14142135623730951f

// ---------------------------------------------------------------------------
// Scratch (device globals)
// ---------------------------------------------------------------------------
__device__ __nv_bfloat16 g_Xh[1024 * 1024];
__device__ __nv_bfloat16 g_Xl[1024 * 1024];
__device__ __nv_bfloat16 g_WhT[2 * PADN * HIN];   // [z][n][k]
__device__ __nv_bfloat16 g_WlT[2 * PADN * HIN];
__device__ float g_proj_s[BB * (ENT + 1) * LL * DD];
__device__ float g_proj_e[BB * (ENT + 1) * LL * DD];
__device__ float g_cd[BB * NMASK];
__device__ float g_fm4[4][BB][LL * LL];           // k-split partial final_mask
__device__ float g_tcos[LL * (DD / 2)];
__device__ float g_tsin[LL * (DD / 2)];
// roped q/k, bf16 hi/lo, [b][e][i][64] (d padded 50->64 with zeros)
__device__ __nv_bfloat16 g_qh[BB * ENT * LL * 64];
__device__ __nv_bfloat16 g_ql[BB * ENT * LL * 64];
__device__ __nv_bfloat16 g_kh[BB * ENT * LL * 64];
__device__ __nv_bfloat16 g_kl[BB * ENT * LL * 64];

// ---------------------------------------------------------------------------
// cp.async helpers (sm_80+ portable PTX)
// ---------------------------------------------------------------------------
__device__ __forceinline__ void cp_async16(void* s, const void* g)
{
    uint32_t sa = (uint32_t)__cvta_generic_to_shared(s);
    asm volatile("cp.async.ca.shared.global [%0], [%1], 16;"
                 :: "r"(sa), "l"(g) : "memory");
}
#define CP_COMMIT() asm volatile("cp.async.commit_group;" ::: "memory")
#define CP_WAIT(n)  asm volatile("cp.async.wait_group %0;" :: "n"(n) : "memory")

// ---------------------------------------------------------------------------
// Prep kernels
// ---------------------------------------------------------------------------
__global__ void split_x(const float* __restrict__ X)
{
    int idx = blockIdx.x * blockDim.x + threadIdx.x;
    if (idx >= 1024 * 1024) return;
    float x = X[idx];
    __nv_bfloat16 h = __float2bfloat16(x);
    __nv_bfloat16 l = __float2bfloat16(x - __bfloat162float(h));
    g_Xh[idx] = h;
    g_Xl[idx] = l;
}

__global__ void split_wT(const float* __restrict__ W0, const float* __restrict__ W1)
{
    __shared__ __nv_bfloat16 th[32][33];
    __shared__ __nv_bfloat16 tl[32][33];
    const int z = blockIdx.z;
    const float* W = z ? W1 : W0;
    const int n0 = blockIdx.x * 32;
    const int k0 = blockIdx.y * 32;
    const int tx = threadIdx.x, ty = threadIdx.y;

    int n = n0 + tx, k = k0 + ty;
    float x = (n < TOT) ? W[(size_t)k * TOT + n] : 0.f;
    __nv_bfloat16 h = __float2bfloat16(x);
    __nv_bfloat16 l = __float2bfloat16(x - __bfloat162float(h));
    th[ty][tx] = h;
    tl[ty][tx] = l;
    __syncthreads();

    int on = n0 + ty, ok = k0 + tx;
    size_t oidx = (size_t)z * PADN * HIN + (size_t)on * HIN + ok;
    g_WhT[oidx] = th[tx][ty];
    g_WlT[oidx] = tl[tx][ty];
}

__global__ void trig_table()
{
    int idx = blockIdx.x * blockDim.x + threadIdx.x;
    if (idx >= LL * (DD / 2)) return;
    int l = idx / (DD / 2), t = idx - l * (DD / 2);
    double inv = exp(-((2.0 * t) / (double)DD) * log(10000.0));
    double ang = (double)l * inv;
    g_tcos[idx] = (float)cos(ang);
    g_tsin[idx] = (float)sin(ang);
}

// ---------------------------------------------------------------------------
// WMMA bf16 GEMM + fused RoPE, 64x64 tile, 2-stage cp.async pipeline.
// grid (14, 16, 2) = 448 blocks, 256 threads / 8 warps.
// warp: wr = wid&3 -> M 16-chunk, wc = wid>>2 -> N 32-chunk.
// ---------------------------------------------------------------------------
struct GemmSmemP {
    union {
        struct {
            __nv_bfloat16 Ah[2][64][40];
            __nv_bfloat16 Al[2][64][40];
            __nv_bfloat16 Bh[2][64][40];
            __nv_bfloat16 Bl[2][64][40];
        } t;                       // 40960 B
        float out[64][68];         // 17408 B
    } u;
};
#define GEMM_SMEM sizeof(GemmSmemP)

__device__ __forceinline__ void gemm_prefetch(
    GemmSmemP* sm, int st, int kc, int m0, int n0, int tid,
    const uint4* Xh4, const uint4* Xl4, const uint4* Bh4, const uint4* Bl4)
{
    const int kc4 = kc * 4;        // 32 bf16 = 4 uint4 per row-chunk
    #pragma unroll
    for (int it = 0; it < 4; it++) {
        int g = it * 256 + tid;    // 0..1023
        int gg = g & 255;
        int row = gg >> 2, c8 = gg & 3;
        if (g < 256) {
            cp_async16(&sm->u.t.Ah[st][row][c8 * 8],
                       Xh4 + (size_t)(m0 + row) * 128 + kc4 + c8);
        } else if (g < 512) {
            cp_async16(&sm->u.t.Al[st][row][c8 * 8],
                       Xl4 + (size_t)(m0 + row) * 128 + kc4 + c8);
        } else if (g < 768) {
            cp_async16(&sm->u.t.Bh[st][row][c8 * 8],
                       Bh4 + (size_t)(n0 + row) * 128 + kc4 + c8);
        } else {
            cp_async16(&sm->u.t.Bl[st][row][c8 * 8],
                       Bl4 + (size_t)(n0 + row) * 128 + kc4 + c8);
        }
    }
}

__global__ __launch_bounds__(256) void gemm_wmma(
    const float* __restrict__ bias0, const float* __restrict__ bias1)
{
    extern __shared__ char dyn[];
    GemmSmemP* sm = reinterpret_cast<GemmSmemP*>(dyn);

    const int z  = blockIdx.z;
    const int n0 = blockIdx.x * 64;
    const int m0 = blockIdx.y * 64;
    const float* bias = z ? bias1 : bias0;
    float* dst        = z ? g_proj_e : g_proj_s;

    const int tid = threadIdx.x;
    const int wid = tid >> 5;
    const int wr = wid & 3;        // M 16-chunk
    const int wc = wid >> 2;       // N 32-chunk

    const uint4* Xh4 = reinterpret_cast<const uint4*>(g_Xh);
    const uint4* Xl4 = reinterpret_cast<const uint4*>(g_Xl);
    const uint4* Bh4 = reinterpret_cast<const uint4*>(g_WhT) + (size_t)z * PADN * 128;
    const uint4* Bl4 = reinterpret_cast<const uint4*>(g_WlT) + (size_t)z * PADN * 128;

    wmma::fragment<wmma::accumulator, 16, 16, 16, float> c[2];
    wmma::fill_fragment(c[0], 0.f);
    wmma::fill_fragment(c[1], 0.f);

    gemm_prefetch(sm, 0, 0, m0, n0, tid, Xh4, Xl4, Bh4, Bl4);
    CP_COMMIT();

    for (int kc = 0; kc < 32; kc++) {
        const int cur = kc & 1;
        if (kc + 1 < 32) {
            gemm_prefetch(sm, cur ^ 1, kc + 1, m0, n0, tid, Xh4, Xl4, Bh4, Bl4);
            CP_COMMIT();
            CP_WAIT(1);
        } else {
            CP_WAIT(0);
        }
        __syncthreads();

        #pragma unroll
        for (int ks = 0; ks < 32; ks += 16) {
            wmma::fragment<wmma::matrix_a, 16, 16, 16, __nv_bfloat16, wmma::row_major> ah, al;
            wmma::fragment<wmma::matrix_b, 16, 16, 16, __nv_bfloat16, wmma::col_major> bh[2], bl[2];
            wmma::load_matrix_sync(ah, &sm->u.t.Ah[cur][wr * 16][ks], 40);
            wmma::load_matrix_sync(al, &sm->u.t.Al[cur][wr * 16][ks], 40);
            #pragma unroll
            for (int j = 0; j < 2; j++) {
                wmma::load_matrix_sync(bh[j], &sm->u.t.Bh[cur][wc * 32 + j * 16][ks], 40);
                wmma::load_matrix_sync(bl[j], &sm->u.t.Bl[cur][wc * 32 + j * 16][ks], 40);
            }
            #pragma unroll
            for (int j = 0; j < 2; j++) {
                wmma::mma_sync(c[j], ah, bh[j], c[j]);
                wmma::mma_sync(c[j], ah, bl[j], c[j]);
                wmma::mma_sync(c[j], al, bh[j], c[j]);
            }
        }
        __syncthreads();
    }

    #pragma unroll
    for (int j = 0; j < 2; j++)
        wmma::store_matrix_sync(&sm->u.out[wr * 16][wc * 32 + j * 16],
                                c[j], 68, wmma::mem_row_major);
    __syncthreads();

    // Epilogue with fused RoPE (even/odd pair per thread; DD even)
    for (int idx = tid; idx < 64 * 32; idx += 256) {
        int row = idx >> 5, cp = idx & 31;
        int n = n0 + cp * 2;
        if (n < TOT) {
            int e = n / DD, d = n - e * DD;
            int m = m0 + row;
            int b = m >> 9, l = m & 511;
            float v0 = sm->u.out[row][cp * 2]     + bias[n];
            float v1 = sm->u.out[row][cp * 2 + 1] + bias[n + 1];
            if (e < ENT) {
                int t = d >> 1;
                float cc = g_tcos[l * (DD / 2) + t];
                float ss = g_tsin[l * (DD / 2) + t];
                float r0 = v0 * cc - v1 * ss;
                float r1 = v1 * cc + v0 * ss;
                v0 = r0; v1 = r1;
            }
            size_t o = (((size_t)b * (ENT + 1) + e) * LL + l) * DD + d;
            dst[o]     = v0;
            dst[o + 1] = v1;
        }
    }
}

// ---------------------------------------------------------------------------
// conj_diag — warp per (b,i), shfl reduce (e=16 slice is never roped)
// ---------------------------------------------------------------------------
__global__ __launch_bounds__(256) void conj_kernel()
{
    int wg = blockIdx.x * 8 + (threadIdx.x >> 5);
    int lane = threadIdx.x & 31;
    if (wg >= BB * NMASK) return;
    int b = wg / NMASK, i = wg - b * NMASK;
    const float* a = g_proj_s + (((size_t)b * (ENT + 1) + ENT) * LL + i) * DD;
    const float* c = g_proj_e + (((size_t)b * (ENT + 1) + ENT) * LL + (i + 1)) * DD;
    float s = 0.f;
    if (lane < DD)      s  = a[lane] * c[lane];
    if (lane + 32 < DD) s += a[lane + 32] * c[lane + 32];
    #pragma unroll
    for (int o = 16; o > 0; o >>= 1)
        s += __shfl_xor_sync(0xFFFFFFFFu, s, o);
    if (lane == 0) g_cd[wg] = s * SCALE;
}

// ---------------------------------------------------------------------------
// split_qk: roped fp32 q/k (e<16) -> bf16 hi/lo, [b][e][i][64], zero-pad d
// ---------------------------------------------------------------------------
__global__ void split_qk()
{
    int idx = blockIdx.x * blockDim.x + threadIdx.x;
    const int total = BB * ENT * LL * 64;
    if (idx >= total) return;
    int d = idx & 63;
    int r = idx >> 6;
    int i = r & 511;  r >>= 9;
    int e = r & 15;   int b = r >> 4;

    float q = 0.f, k = 0.f;
    if (d < DD) {
        size_t src = (((size_t)b * (ENT + 1) + e) * LL + i) * DD + d;
        q = g_proj_s[src];
        k = g_proj_e[src];
    }
    __nv_bfloat16 qh = __float2bfloat16(q);
    __nv_bfloat16 kh = __float2bfloat16(k);
    g_qh[idx] = qh;
    g_ql[idx] = __float2bfloat16(q - __bfloat162float(qh));
    g_kh[idx] = kh;
    g_kl[idx] = __float2bfloat16(k - __bfloat162float(kh));
}

// ---------------------------------------------------------------------------
// mask_kernel — R1 inner shape, k-split x4 (z) against wave quantization.
// grid (32, 32, 4) = 4096 blocks; partials to g_fm4[z].
// ---------------------------------------------------------------------------
__global__ __launch_bounds__(256) void mask_kernel(const float* __restrict__ mask)
{
    __shared__ float scd[BB * NMASK];
    const int tid = threadIdx.x;
    const int tx = tid & 15, ty = tid >> 4;

    for (int k = tid; k < BB * NMASK; k += 256) scd[k] = g_cd[k];

    const int i0 = blockIdx.y * 16, j0 = blockIdx.x * 16;
    const int ks = blockIdx.z;
    const int i = i0 + ty, j = j0 + tx;

    const int kbeg = ks * 128;
    const int kend = (ks == 3) ? NMASK : kbeg + 128;
    const float* mp = mask + (size_t)kbeg * (LL * LL) + (size_t)i * LL + j;

    __syncthreads();

    float a0 = 0.f, a1 = 0.f;
    int k = kbeg;
    for (; k + 16 <= kend; k += 16) {
        float m[16];
        #pragma unroll
        for (int u = 0; u < 16; u++)
            m[u] = mp[(size_t)(k - kbeg + u) * (LL * LL)];
        #pragma unroll
        for (int u = 0; u < 16; u++) {
            a0 = fmaf(scd[k + u],          m[u], a0);
            a1 = fmaf(scd[NMASK + k + u],  m[u], a1);
        }
    }
    for (; k < kend; k++) {
        float m = mp[(size_t)(k - kbeg) * (LL * LL)];
        a0 = fmaf(scd[k],         m, a0);
        a1 = fmaf(scd[NMASK + k], m, a1);
    }

    g_fm4[ks][0][(size_t)i * LL + j] = a0;
    g_fm4[ks][1][(size_t)i * LL + j] = a1;
}

// ---------------------------------------------------------------------------
// scores_wmma (R11 shape): (b, 32i x 32j) per block, split-bf16 WMMA.
// Epilogue sums the 4 k-split mask partials.
// ---------------------------------------------------------------------------
#define SS_LD   36
#define TILE_LD 72
#define SMEM_SS_BYTES   (16 * 32 * SS_LD * 4)
#define SMEM_TILE_BYTES (8 * 32 * TILE_LD * 2)
#define SCORES_SMEM     (SMEM_SS_BYTES + SMEM_TILE_BYTES)

__global__ __launch_bounds__(256) void scores_wmma(float* __restrict__ out)
{
    extern __shared__ char smem[];
    float* sS = reinterpret_cast<float*>(smem);
    __nv_bfloat16* tiles = reinterpret_cast<__nv_bfloat16*>(smem + SMEM_SS_BYTES);

    const int tid = threadIdx.x;
    const int wid = tid >> 5;
    const int j0 = blockIdx.x * 32;
    const int i0 = blockIdx.y * 32;
    const int b  = blockIdx.z;

    const uint4* qh4 = reinterpret_cast<const uint4*>(g_qh);
    const uint4* ql4 = reinterpret_cast<const uint4*>(g_ql);
    const uint4* kh4 = reinterpret_cast<const uint4*>(g_kh);
    const uint4* kl4 = reinterpret_cast<const uint4*>(g_kl);

    for (int ep = 0; ep < 8; ep++) {
        const int e0 = ep * 2;
        __syncthreads();
        #pragma unroll
        for (int it = 0; it < 8; it++) {
            int g = it * 256 + tid;
            int c   = g & 7;
            int r   = (g >> 3) & 31;
            int mat = g >> 8;
            int hl = mat & 1, el = (mat >> 1) & 1, qk = mat >> 2;
            const uint4* src = qk ? (hl ? kl4 : kh4) : (hl ? ql4 : qh4);
            int row0 = qk ? j0 : i0;
            size_t gi = ((size_t)(b * ENT + e0 + el) * LL + row0 + r) * 8 + c;
            uint4 v = src[gi];
            *reinterpret_cast<uint4*>(
                &tiles[((qk * 4 + el * 2 + hl) * 32 + r) * TILE_LD + c * 8]) = v;
        }
        __syncthreads();

        const int el  = wid >> 2;
        const int qi  = ((wid >> 1) & 1) * 16;
        const int qj  = (wid & 1) * 16;
        const __nv_bfloat16* Qh_ = &tiles[((el * 2 + 0) * 32 + qi) * TILE_LD];
        const __nv_bfloat16* Ql_ = &tiles[((el * 2 + 1) * 32 + qi) * TILE_LD];
        const __nv_bfloat16* Kh_ = &tiles[((4 + el * 2 + 0) * 32 + qj) * TILE_LD];
        const __nv_bfloat16* Kl_ = &tiles[((4 + el * 2 + 1) * 32 + qj) * TILE_LD];

        wmma::fragment<wmma::accumulator, 16, 16, 16, float> acc;
        wmma::fill_fragment(acc, 0.f);
        #pragma unroll
        for (int ks = 0; ks < 64; ks += 16) {
            wmma::fragment<wmma::matrix_a, 16, 16, 16, __nv_bfloat16, wmma::row_major> ah, al;
            wmma::fragment<wmma::matrix_b, 16, 16, 16, __nv_bfloat16, wmma::col_major> bh, bl;
            wmma::load_matrix_sync(ah, Qh_ + ks, TILE_LD);
            wmma::load_matrix_sync(al, Ql_ + ks, TILE_LD);
            wmma::load_matrix_sync(bh, Kh_ + ks, TILE_LD);
            wmma::load_matrix_sync(bl, Kl_ + ks, TILE_LD);
            wmma::mma_sync(acc, ah, bh, acc);
            wmma::mma_sync(acc, ah, bl, acc);
            wmma::mma_sync(acc, al, bh, acc);
        }
        wmma::store_matrix_sync(&sS[(e0 + el) * 32 * SS_LD + qi * SS_LD + qj],
                                acc, SS_LD, wmma::mem_row_major);
    }
    __syncthreads();

    for (int v = 0; v < 4; v++) {
        int lin = v * 256 + tid;
        int jj = lin & 31, ii = lin >> 5;
        int i = i0 + ii, j = j0 + jj;
        size_t fidx = (size_t)i * LL + j;
        float fm = (g_fm4[0][b][fidx] + g_fm4[1][b][fidx]) +
                   (g_fm4[2][b][fidx] + g_fm4[3][b][fidx]);
        float* op = out + ((((size_t)b * LL + i) * LL + j) * ENT);
        const float* sp = &sS[ii * SS_LD + jj];
        #pragma unroll
        for (int q = 0; q < 4; q++) {
            float4 w;
            w.x = fmaf(sp[(4 * q + 0) * 32 * SS_LD], SCALE, fm);
            w.y = fmaf(sp[(4 * q + 1) * 32 * SS_LD], SCALE, fm);
            w.z = fmaf(sp[(4 * q + 2) * 32 * SS_LD], SCALE, fm);
            w.w = fmaf(sp[(4 * q + 3) * 32 * SS_LD], SCALE, fm);
            *reinterpret_cast<float4*>(op + 4 * q) = w;
        }
    }
}

// ---------------------------------------------------------------------------
extern "C" void kernel_launch(void* const* d_in, const int* in_sizes, int n_in,
                              void* d_out, int out_size)
{
    const float* X    = (const float*)d_in[0];
    const float* mask = (const float*)d_in[1];
    const float* Ws   = (const float*)d_in[2];
    const float* bs   = (const float*)d_in[3];
    const float* We   = (const float*)d_in[4];
    const float* be   = (const float*)d_in[5];
    float* out        = (float*)d_out;

    cudaFuncSetAttribute(scores_wmma,
        cudaFuncAttributeMaxDynamicSharedMemorySize, SCORES_SMEM);
    cudaFuncSetAttribute(gemm_wmma,
        cudaFuncAttributeMaxDynamicSharedMemorySize, GEMM_SMEM);

    split_x<<<(1024 * 1024 + 255) / 256, 256>>>(X);
    split_wT<<<dim3(PADN / 32, HIN / 32, 2), dim3(32, 32)>>>(Ws, We);
    trig_table<<<(LL * (DD / 2) + 255) / 256, 256>>>();

    gemm_wmma<<<dim3(PADN / 64, 1024 / 64, 2), 256, GEMM_SMEM>>>(bs, be);

    conj_kernel<<<(BB * NMASK + 7) / 8, 256>>>();
    split_qk<<<(BB * ENT * LL * 64 + 255) / 256, 256>>>();

    mask_kernel<<<dim3(LL / 16, LL / 16, 4), 256>>>(mask);
    scores_wmma<<<dim3(LL / 32, LL / 32, 2), 256, SCORES_SMEM>>>(out);
}

// round 15
// speedup vs baseline: 1.1390x; 1.0092x over previous
#include <cuda_runtime.h>
#include <cuda_bf16.h>
#include <mma.h>
#include <cstdint>
#include <cstddef>

using namespace nvcuda;

#define BB   2
#define LL   512
#define HIN  1024
#define ENT  16
#define DD   50
#define TOT  850
#define PADN 896
#define NMASK 511
#define SCALE 0.14142135623730951f

// ---------------------------------------------------------------------------
// Scratch (device globals)
// ---------------------------------------------------------------------------
__device__ __nv_bfloat16 g_Xh[1024 * 1024];
__device__ __nv_bfloat16 g_Xl[1024 * 1024];
__device__ __nv_bfloat16 g_WhT[2 * PADN * HIN];   // [z][n][k]
__device__ __nv_bfloat16 g_WlT[2 * PADN * HIN];
__device__ float g_conj_s[BB * LL * DD];          // e=16 slice only
__device__ float g_conj_e[BB * LL * DD];
__device__ float g_cd[BB * NMASK];
__device__ float g_fm4[4][BB][LL * LL];           // k-split partial final_mask
__device__ float g_tcos[LL * (DD / 2)];
__device__ float g_tsin[LL * (DD / 2)];
// roped q/k, bf16 hi/lo, [b][e][i][64] (d padded 50->64 with zeros)
__device__ __nv_bfloat16 g_qh[BB * ENT * LL * 64];
__device__ __nv_bfloat16 g_ql[BB * ENT * LL * 64];
__device__ __nv_bfloat16 g_kh[BB * ENT * LL * 64];
__device__ __nv_bfloat16 g_kl[BB * ENT * LL * 64];

// ---------------------------------------------------------------------------
// cp.async helpers (sm_80+ portable PTX)
// ---------------------------------------------------------------------------
__device__ __forceinline__ void cp_async16(void* s, const void* g)
{
    uint32_t sa = (uint32_t)__cvta_generic_to_shared(s);
    asm volatile("cp.async.ca.shared.global [%0], [%1], 16;"
                 :: "r"(sa), "l"(g) : "memory");
}
#define CP_COMMIT() asm volatile("cp.async.commit_group;" ::: "memory")
#define CP_WAIT(n)  asm volatile("cp.async.wait_group %0;" :: "n"(n) : "memory")

// ---------------------------------------------------------------------------
// Prep kernels
// ---------------------------------------------------------------------------
__global__ void split_x(const float* __restrict__ X)
{
    int idx = blockIdx.x * blockDim.x + threadIdx.x;
    if (idx >= 1024 * 1024) return;
    float x = X[idx];
    __nv_bfloat16 h = __float2bfloat16(x);
    __nv_bfloat16 l = __float2bfloat16(x - __bfloat162float(h));
    g_Xh[idx] = h;
    g_Xl[idx] = l;
}

__global__ void split_wT(const float* __restrict__ W0, const float* __restrict__ W1)
{
    __shared__ __nv_bfloat16 th[32][33];
    __shared__ __nv_bfloat16 tl[32][33];
    const int z = blockIdx.z;
    const float* W = z ? W1 : W0;
    const int n0 = blockIdx.x * 32;
    const int k0 = blockIdx.y * 32;
    const int tx = threadIdx.x, ty = threadIdx.y;

    int n = n0 + tx, k = k0 + ty;
    float x = (n < TOT) ? W[(size_t)k * TOT + n] : 0.f;
    __nv_bfloat16 h = __float2bfloat16(x);
    __nv_bfloat16 l = __float2bfloat16(x - __bfloat162float(h));
    th[ty][tx] = h;
    tl[ty][tx] = l;
    __syncthreads();

    int on = n0 + ty, ok = k0 + tx;
    size_t oidx = (size_t)z * PADN * HIN + (size_t)on * HIN + ok;
    g_WhT[oidx] = th[tx][ty];
    g_WlT[oidx] = tl[tx][ty];
}

__global__ void trig_table()
{
    int idx = blockIdx.x * blockDim.x + threadIdx.x;
    if (idx >= LL * (DD / 2)) return;
    int l = idx / (DD / 2), t = idx - l * (DD / 2);
    double inv = exp(-((2.0 * t) / (double)DD) * log(10000.0));
    double ang = (double)l * inv;
    g_tcos[idx] = (float)cos(ang);
    g_tsin[idx] = (float)sin(ang);
}

// Zero the d=50..63 pads of qh/ql/kh/kl (gemm epilogue only writes d<50).
__global__ void pad_zero()
{
    int idx = blockIdx.x * blockDim.x + threadIdx.x;
    const int per = BB * ENT * LL * 14;           // 229376 pads per array
    if (idx >= 4 * per) return;
    int arr = idx / per;
    int r = idx - arr * per;
    int dp = r % 14;
    int row = r / 14;                              // b*ENT*LL + e*LL + i
    __nv_bfloat16* a = (arr == 0) ? g_qh : (arr == 1) ? g_ql
                      : (arr == 2) ? g_kh : g_kl;
    a[(size_t)row * 64 + 50 + dp] = __float2bfloat16(0.f);
}

// ---------------------------------------------------------------------------
// WMMA bf16 GEMM + fused RoPE + fused bf16 hi/lo split in epilogue.
// 64x64 tile, 2-stage cp.async pipeline, grid (14, 16, 2), 256 threads.
// ---------------------------------------------------------------------------
struct GemmSmemP {
    union {
        struct {
            __nv_bfloat16 Ah[2][64][40];
            __nv_bfloat16 Al[2][64][40];
            __nv_bfloat16 Bh[2][64][40];
            __nv_bfloat16 Bl[2][64][40];
        } t;                       // 40960 B
        float out[64][68];         // 17408 B
    } u;
};
#define GEMM_SMEM sizeof(GemmSmemP)

__device__ __forceinline__ void gemm_prefetch(
    GemmSmemP* sm, int st, int kc, int m0, int n0, int tid,
    const uint4* Xh4, const uint4* Xl4, const uint4* Bh4, const uint4* Bl4)
{
    const int kc4 = kc * 4;
    #pragma unroll
    for (int it = 0; it < 4; it++) {
        int g = it * 256 + tid;
        int gg = g & 255;
        int row = gg >> 2, c8 = gg & 3;
        if (g < 256) {
            cp_async16(&sm->u.t.Ah[st][row][c8 * 8],
                       Xh4 + (size_t)(m0 + row) * 128 + kc4 + c8);
        } else if (g < 512) {
            cp_async16(&sm->u.t.Al[st][row][c8 * 8],
                       Xl4 + (size_t)(m0 + row) * 128 + kc4 + c8);
        } else if (g < 768) {
            cp_async16(&sm->u.t.Bh[st][row][c8 * 8],
                       Bh4 + (size_t)(n0 + row) * 128 + kc4 + c8);
        } else {
            cp_async16(&sm->u.t.Bl[st][row][c8 * 8],
                       Bl4 + (size_t)(n0 + row) * 128 + kc4 + c8);
        }
    }
}

__global__ __launch_bounds__(256) void gemm_wmma(
    const float* __restrict__ bias0, const float* __restrict__ bias1)
{
    extern __shared__ char dyn[];
    GemmSmemP* sm = reinterpret_cast<GemmSmemP*>(dyn);

    const int z  = blockIdx.z;
    const int n0 = blockIdx.x * 64;
    const int m0 = blockIdx.y * 64;
    const float* bias = z ? bias1 : bias0;

    const int tid = threadIdx.x;
    const int wid = tid >> 5;
    const int wr = wid & 3;
    const int wc = wid >> 2;

    const uint4* Xh4 = reinterpret_cast<const uint4*>(g_Xh);
    const uint4* Xl4 = reinterpret_cast<const uint4*>(g_Xl);
    const uint4* Bh4 = reinterpret_cast<const uint4*>(g_WhT) + (size_t)z * PADN * 128;
    const uint4* Bl4 = reinterpret_cast<const uint4*>(g_WlT) + (size_t)z * PADN * 128;

    wmma::fragment<wmma::accumulator, 16, 16, 16, float> c[2];
    wmma::fill_fragment(c[0], 0.f);
    wmma::fill_fragment(c[1], 0.f);

    gemm_prefetch(sm, 0, 0, m0, n0, tid, Xh4, Xl4, Bh4, Bl4);
    CP_COMMIT();

    for (int kc = 0; kc < 32; kc++) {
        const int cur = kc & 1;
        if (kc + 1 < 32) {
            gemm_prefetch(sm, cur ^ 1, kc + 1, m0, n0, tid, Xh4, Xl4, Bh4, Bl4);
            CP_COMMIT();
            CP_WAIT(1);
        } else {
            CP_WAIT(0);
        }
        __syncthreads();

        #pragma unroll
        for (int ks = 0; ks < 32; ks += 16) {
            wmma::fragment<wmma::matrix_a, 16, 16, 16, __nv_bfloat16, wmma::row_major> ah, al;
            wmma::fragment<wmma::matrix_b, 16, 16, 16, __nv_bfloat16, wmma::col_major> bh[2], bl[2];
            wmma::load_matrix_sync(ah, &sm->u.t.Ah[cur][wr * 16][ks], 40);
            wmma::load_matrix_sync(al, &sm->u.t.Al[cur][wr * 16][ks], 40);
            #pragma unroll
            for (int j = 0; j < 2; j++) {
                wmma::load_matrix_sync(bh[j], &sm->u.t.Bh[cur][wc * 32 + j * 16][ks], 40);
                wmma::load_matrix_sync(bl[j], &sm->u.t.Bl[cur][wc * 32 + j * 16][ks], 40);
            }
            #pragma unroll
            for (int j = 0; j < 2; j++) {
                wmma::mma_sync(c[j], ah, bh[j], c[j]);
                wmma::mma_sync(c[j], ah, bl[j], c[j]);
                wmma::mma_sync(c[j], al, bh[j], c[j]);
            }
        }
        __syncthreads();
    }

    #pragma unroll
    for (int j = 0; j < 2; j++)
        wmma::store_matrix_sync(&sm->u.out[wr * 16][wc * 32 + j * 16],
                                c[j], 68, wmma::mem_row_major);
    __syncthreads();

    // Epilogue: bias + RoPE + bf16 hi/lo split, written straight to the
    // scores operand arrays (q for z=0, k for z=1). e=16 stays fp32 for conj.
    __nv_bfloat16* dh = z ? g_kh : g_qh;
    __nv_bfloat16* dl = z ? g_kl : g_ql;
    float* conj_dst   = z ? g_conj_e : g_conj_s;

    for (int idx = tid; idx < 64 * 32; idx += 256) {
        int row = idx >> 5, cp = idx & 31;
        int n = n0 + cp * 2;
        if (n < TOT) {
            int e = n / DD, d = n - e * DD;      // d even
            int m = m0 + row;
            int b = m >> 9, l = m & 511;
            float v0 = sm->u.out[row][cp * 2]     + bias[n];
            float v1 = sm->u.out[row][cp * 2 + 1] + bias[n + 1];
            if (e < ENT) {
                int t = d >> 1;
                float cc = g_tcos[l * (DD / 2) + t];
                float ss = g_tsin[l * (DD / 2) + t];
                float r0 = v0 * cc - v1 * ss;
                float r1 = v1 * cc + v0 * ss;
                __nv_bfloat16 h0 = __float2bfloat16(r0);
                __nv_bfloat16 h1 = __float2bfloat16(r1);
                __nv_bfloat16 l0 = __float2bfloat16(r0 - __bfloat162float(h0));
                __nv_bfloat16 l1 = __float2bfloat16(r1 - __bfloat162float(h1));
                size_t o = (((size_t)(b * ENT + e)) * LL + l) * 64 + d;
                *reinterpret_cast<__nv_bfloat162*>(&dh[o]) =
                    __nv_bfloat162(h0, h1);
                *reinterpret_cast<__nv_bfloat162*>(&dl[o]) =
                    __nv_bfloat162(l0, l1);
            } else {
                size_t o = ((size_t)b * LL + l) * DD + d;
                conj_dst[o]     = v0;
                conj_dst[o + 1] = v1;
            }
        }
    }
}

// ---------------------------------------------------------------------------
// conj_diag — warp per (b,i), shfl reduce (fp32 e=16 slice)
// ---------------------------------------------------------------------------
__global__ __launch_bounds__(256) void conj_kernel()
{
    int wg = blockIdx.x * 8 + (threadIdx.x >> 5);
    int lane = threadIdx.x & 31;
    if (wg >= BB * NMASK) return;
    int b = wg / NMASK, i = wg - b * NMASK;
    const float* a = g_conj_s + ((size_t)b * LL + i) * DD;
    const float* c = g_conj_e + ((size_t)b * LL + i + 1) * DD;
    float s = 0.f;
    if (lane < DD)      s  = a[lane] * c[lane];
    if (lane + 32 < DD) s += a[lane + 32] * c[lane + 32];
    #pragma unroll
    for (int o = 16; o > 0; o >>= 1)
        s += __shfl_xor_sync(0xFFFFFFFFu, s, o);
    if (lane == 0) g_cd[wg] = s * SCALE;
}

// ---------------------------------------------------------------------------
// mask_kernel — 8i x 32j tile: each warp streams full 128B lines.
// k-split x4 via z. grid (16, 64, 4) = 4096 blocks, 256 threads.
// ---------------------------------------------------------------------------
__global__ __launch_bounds__(256) void mask_kernel(const float* __restrict__ mask)
{
    __shared__ float scd[BB * NMASK];
    const int tid = threadIdx.x;
    const int jx = tid & 31, ty = tid >> 5;   // warp = one row of 32 j

    for (int k = tid; k < BB * NMASK; k += 256) scd[k] = g_cd[k];

    const int i0 = blockIdx.y * 8, j0 = blockIdx.x * 32;
    const int ks = blockIdx.z;
    const int i = i0 + ty, j = j0 + jx;

    const int kbeg = ks * 128;
    const int kend = (ks == 3) ? NMASK : kbeg + 128;
    const float* mp = mask + (size_t)kbeg * (LL * LL) + (size_t)i * LL + j;

    __syncthreads();

    float a0 = 0.f, a1 = 0.f;
    int k = kbeg;
    for (; k + 16 <= kend; k += 16) {
        float m[16];
        #pragma unroll
        for (int u = 0; u < 16; u++)
            m[u] = mp[(size_t)(k - kbeg + u) * (LL * LL)];
        #pragma unroll
        for (int u = 0; u < 16; u++) {
            a0 = fmaf(scd[k + u],          m[u], a0);
            a1 = fmaf(scd[NMASK + k + u],  m[u], a1);
        }
    }
    for (; k < kend; k++) {
        float m = mp[(size_t)(k - kbeg) * (LL * LL)];
        a0 = fmaf(scd[k],         m, a0);
        a1 = fmaf(scd[NMASK + k], m, a1);
    }

    g_fm4[ks][0][(size_t)i * LL + j] = a0;
    g_fm4[ks][1][(size_t)i * LL + j] = a1;
}

// ---------------------------------------------------------------------------
// scores_wmma (R11 shape): (b, 32i x 32j) per block, split-bf16 WMMA.
// Epilogue sums the 4 k-split mask partials.
// ---------------------------------------------------------------------------
#define SS_LD   36
#define TILE_LD 72
#define SMEM_SS_BYTES   (16 * 32 * SS_LD * 4)
#define SMEM_TILE_BYTES (8 * 32 * TILE_LD * 2)
#define SCORES_SMEM     (SMEM_SS_BYTES + SMEM_TILE_BYTES)

__global__ __launch_bounds__(256) void scores_wmma(float* __restrict__ out)
{
    extern __shared__ char smem[];
    float* sS = reinterpret_cast<float*>(smem);
    __nv_bfloat16* tiles = reinterpret_cast<__nv_bfloat16*>(smem + SMEM_SS_BYTES);

    const int tid = threadIdx.x;
    const int wid = tid >> 5;
    const int j0 = blockIdx.x * 32;
    const int i0 = blockIdx.y * 32;
    const int b  = blockIdx.z;

    const uint4* qh4 = reinterpret_cast<const uint4*>(g_qh);
    const uint4* ql4 = reinterpret_cast<const uint4*>(g_ql);
    const uint4* kh4 = reinterpret_cast<const uint4*>(g_kh);
    const uint4* kl4 = reinterpret_cast<const uint4*>(g_kl);

    for (int ep = 0; ep < 8; ep++) {
        const int e0 = ep * 2;
        __syncthreads();
        #pragma unroll
        for (int it = 0; it < 8; it++) {
            int g = it * 256 + tid;
            int c   = g & 7;
            int r   = (g >> 3) & 31;
            int mat = g >> 8;
            int hl = mat & 1, el = (mat >> 1) & 1, qk = mat >> 2;
            const uint4* src = qk ? (hl ? kl4 : kh4) : (hl ? ql4 : qh4);
            int row0 = qk ? j0 : i0;
            size_t gi = ((size_t)(b * ENT + e0 + el) * LL + row0 + r) * 8 + c;
            uint4 v = src[gi];
            *reinterpret_cast<uint4*>(
                &tiles[((qk * 4 + el * 2 + hl) * 32 + r) * TILE_LD + c * 8]) = v;
        }
        __syncthreads();

        const int el  = wid >> 2;
        const int qi  = ((wid >> 1) & 1) * 16;
        const int qj  = (wid & 1) * 16;
        const __nv_bfloat16* Qh_ = &tiles[((el * 2 + 0) * 32 + qi) * TILE_LD];
        const __nv_bfloat16* Ql_ = &tiles[((el * 2 + 1) * 32 + qi) * TILE_LD];
        const __nv_bfloat16* Kh_ = &tiles[((4 + el * 2 + 0) * 32 + qj) * TILE_LD];
        const __nv_bfloat16* Kl_ = &tiles[((4 + el * 2 + 1) * 32 + qj) * TILE_LD];

        wmma::fragment<wmma::accumulator, 16, 16, 16, float> acc;
        wmma::fill_fragment(acc, 0.f);
        #pragma unroll
        for (int ks = 0; ks < 64; ks += 16) {
            wmma::fragment<wmma::matrix_a, 16, 16, 16, __nv_bfloat16, wmma::row_major> ah, al;
            wmma::fragment<wmma::matrix_b, 16, 16, 16, __nv_bfloat16, wmma::col_major> bh, bl;
            wmma::load_matrix_sync(ah, Qh_ + ks, TILE_LD);
            wmma::load_matrix_sync(al, Ql_ + ks, TILE_LD);
            wmma::load_matrix_sync(bh, Kh_ + ks, TILE_LD);
            wmma::load_matrix_sync(bl, Kl_ + ks, TILE_LD);
            wmma::mma_sync(acc, ah, bh, acc);
            wmma::mma_sync(acc, ah, bl, acc);
            wmma::mma_sync(acc, al, bh, acc);
        }
        wmma::store_matrix_sync(&sS[(e0 + el) * 32 * SS_LD + qi * SS_LD + qj],
                                acc, SS_LD, wmma::mem_row_major);
    }
    __syncthreads();

    for (int v = 0; v < 4; v++) {
        int lin = v * 256 + tid;
        int jj = lin & 31, ii = lin >> 5;
        int i = i0 + ii, j = j0 + jj;
        size_t fidx = (size_t)i * LL + j;
        float fm = (g_fm4[0][b][fidx] + g_fm4[1][b][fidx]) +
                   (g_fm4[2][b][fidx] + g_fm4[3][b][fidx]);
        float* op = out + ((((size_t)b * LL + i) * LL + j) * ENT);
        const float* sp = &sS[ii * SS_LD + jj];
        #pragma unroll
        for (int q = 0; q < 4; q++) {
            float4 w;
            w.x = fmaf(sp[(4 * q + 0) * 32 * SS_LD], SCALE, fm);
            w.y = fmaf(sp[(4 * q + 1) * 32 * SS_LD], SCALE, fm);
            w.z = fmaf(sp[(4 * q + 2) * 32 * SS_LD], SCALE, fm);
            w.w = fmaf(sp[(4 * q + 3) * 32 * SS_LD], SCALE, fm);
            *reinterpret_cast<float4*>(op + 4 * q) = w;
        }
    }
}

// ---------------------------------------------------------------------------
extern "C" void kernel_launch(void* const* d_in, const int* in_sizes, int n_in,
                              void* d_out, int out_size)
{
    const float* X    = (const float*)d_in[0];
    const float* mask = (const float*)d_in[1];
    const float* Ws   = (const float*)d_in[2];
    const float* bs   = (const float*)d_in[3];
    const float* We   = (const float*)d_in[4];
    const float* be   = (const float*)d_in[5];
    float* out        = (float*)d_out;

    cudaFuncSetAttribute(scores_wmma,
        cudaFuncAttributeMaxDynamicSharedMemorySize, SCORES_SMEM);
    cudaFuncSetAttribute(gemm_wmma,
        cudaFuncAttributeMaxDynamicSharedMemorySize, GEMM_SMEM);

    split_x<<<(1024 * 1024 + 255) / 256, 256>>>(X);
    split_wT<<<dim3(PADN / 32, HIN / 32, 2), dim3(32, 32)>>>(Ws, We);
    trig_table<<<(LL * (DD / 2) + 255) / 256, 256>>>();
    pad_zero<<<(4 * BB * ENT * LL * 14 + 255) / 256, 256>>>();

    gemm_wmma<<<dim3(PADN / 64, 1024 / 64, 2), 256, GEMM_SMEM>>>(bs, be);

    conj_kernel<<<(BB * NMASK + 7) / 8, 256>>>();

    mask_kernel<<<dim3(LL / 32, LL / 8, 4), 256>>>(mask);
    scores_wmma<<<dim3(LL / 32, LL / 32, 2), 256, SCORES_SMEM>>>(out);
}

// round 16
// speedup vs baseline: 1.2192x; 1.0704x over previous
#include <cuda_runtime.h>
#include <cuda_bf16.h>
#include <mma.h>
#include <cstdint>
#include <cstddef>

using namespace nvcuda;

#define BB   2
#define LL   512
#define HIN  1024
#define ENT  16
#define DD   50
#define TOT  850
#define PADN 896
#define NMASK 511
#define SCALE 0.14142135623730951f

// ---------------------------------------------------------------------------
// Scratch (device globals)
// ---------------------------------------------------------------------------
__device__ __nv_bfloat16 g_Xh[1024 * 1024];
__device__ __nv_bfloat16 g_Xl[1024 * 1024];
__device__ __nv_bfloat16 g_WhT[2 * PADN * HIN];   // [z][n][k]
__device__ __nv_bfloat16 g_WlT[2 * PADN * HIN];
__device__ float g_conj_s[BB * LL * DD];          // e=16 slice only
__device__ float g_conj_e[BB * LL * DD];
__device__ float g_cd[BB * NMASK];
__device__ float g_fm4[4][BB][LL * LL];           // k-split partial final_mask
__device__ float g_tcos[LL * (DD / 2)];
__device__ float g_tsin[LL * (DD / 2)];
// roped q/k, bf16 hi/lo, [b][e][i][64] (d padded 50->64 with zeros)
__device__ __nv_bfloat16 g_qh[BB * ENT * LL * 64];
__device__ __nv_bfloat16 g_ql[BB * ENT * LL * 64];
__device__ __nv_bfloat16 g_kh[BB * ENT * LL * 64];
__device__ __nv_bfloat16 g_kl[BB * ENT * LL * 64];

// ---------------------------------------------------------------------------
// cp.async helpers (sm_80+ portable PTX)
// ---------------------------------------------------------------------------
__device__ __forceinline__ void cp_async16(void* s, const void* g)
{
    uint32_t sa = (uint32_t)__cvta_generic_to_shared(s);
    asm volatile("cp.async.ca.shared.global [%0], [%1], 16;"
                 :: "r"(sa), "l"(g) : "memory");
}
#define CP_COMMIT() asm volatile("cp.async.commit_group;" ::: "memory")
#define CP_WAIT(n)  asm volatile("cp.async.wait_group %0;" :: "n"(n) : "memory")

// ---------------------------------------------------------------------------
// Prep kernels
// ---------------------------------------------------------------------------
__global__ void split_x(const float* __restrict__ X)
{
    int idx = blockIdx.x * blockDim.x + threadIdx.x;   // 262144 float4s
    if (idx >= 1024 * 1024 / 4) return;
    float4 v = reinterpret_cast<const float4*>(X)[idx];
    __nv_bfloat16 h0 = __float2bfloat16(v.x), h1 = __float2bfloat16(v.y);
    __nv_bfloat16 h2 = __float2bfloat16(v.z), h3 = __float2bfloat16(v.w);
    __nv_bfloat16 l0 = __float2bfloat16(v.x - __bfloat162float(h0));
    __nv_bfloat16 l1 = __float2bfloat16(v.y - __bfloat162float(h1));
    __nv_bfloat16 l2 = __float2bfloat16(v.z - __bfloat162float(h2));
    __nv_bfloat16 l3 = __float2bfloat16(v.w - __bfloat162float(h3));
    __nv_bfloat162* Hp = reinterpret_cast<__nv_bfloat162*>(g_Xh);
    __nv_bfloat162* Lp = reinterpret_cast<__nv_bfloat162*>(g_Xl);
    Hp[idx * 2]     = __nv_bfloat162(h0, h1);
    Hp[idx * 2 + 1] = __nv_bfloat162(h2, h3);
    Lp[idx * 2]     = __nv_bfloat162(l0, l1);
    Lp[idx * 2 + 1] = __nv_bfloat162(l2, l3);
}

__global__ void split_wT(const float* __restrict__ W0, const float* __restrict__ W1)
{
    __shared__ __nv_bfloat16 th[32][33];
    __shared__ __nv_bfloat16 tl[32][33];
    const int z = blockIdx.z;
    const float* W = z ? W1 : W0;
    const int n0 = blockIdx.x * 32;
    const int k0 = blockIdx.y * 32;
    const int tx = threadIdx.x, ty = threadIdx.y;

    int n = n0 + tx, k = k0 + ty;
    float x = (n < TOT) ? W[(size_t)k * TOT + n] : 0.f;
    __nv_bfloat16 h = __float2bfloat16(x);
    __nv_bfloat16 l = __float2bfloat16(x - __bfloat162float(h));
    th[ty][tx] = h;
    tl[ty][tx] = l;
    __syncthreads();

    int on = n0 + ty, ok = k0 + tx;
    size_t oidx = (size_t)z * PADN * HIN + (size_t)on * HIN + ok;
    g_WhT[oidx] = th[tx][ty];
    g_WlT[oidx] = tl[tx][ty];
}

__global__ void trig_table()
{
    int idx = blockIdx.x * blockDim.x + threadIdx.x;
    if (idx >= LL * (DD / 2)) return;
    int l = idx / (DD / 2), t = idx - l * (DD / 2);
    double inv = exp(-((2.0 * t) / (double)DD) * log(10000.0));
    double ang = (double)l * inv;
    g_tcos[idx] = (float)cos(ang);
    g_tsin[idx] = (float)sin(ang);
}

// Zero the d=50..63 pads of qh/ql/kh/kl: one thread per (array,row),
// 7 x 4B stores each (offset 100 within the 128B row is 4B-aligned).
__global__ void pad_zero()
{
    int idx = blockIdx.x * blockDim.x + threadIdx.x;
    const int rows = BB * ENT * LL;               // 16384 per array
    if (idx >= 4 * rows) return;
    int arr = idx >> 14;
    int row = idx & (rows - 1);
    __nv_bfloat16* a = (arr == 0) ? g_qh : (arr == 1) ? g_ql
                      : (arr == 2) ? g_kh : g_kl;
    uint32_t* p = reinterpret_cast<uint32_t*>(&a[(size_t)row * 64 + 50]);
    #pragma unroll
    for (int u = 0; u < 7; u++) p[u] = 0u;
}

// ---------------------------------------------------------------------------
// WMMA bf16 GEMM + fused RoPE + fused bf16 hi/lo split in epilogue.
// 64x64 tile, 2-stage cp.async pipeline, grid (14, 16, 2), 256 threads.
// ---------------------------------------------------------------------------
struct GemmSmemP {
    union {
        struct {
            __nv_bfloat16 Ah[2][64][40];
            __nv_bfloat16 Al[2][64][40];
            __nv_bfloat16 Bh[2][64][40];
            __nv_bfloat16 Bl[2][64][40];
        } t;
        float out[64][68];
    } u;
};
#define GEMM_SMEM sizeof(GemmSmemP)

__device__ __forceinline__ void gemm_prefetch(
    GemmSmemP* sm, int st, int kc, int m0, int n0, int tid,
    const uint4* Xh4, const uint4* Xl4, const uint4* Bh4, const uint4* Bl4)
{
    const int kc4 = kc * 4;
    #pragma unroll
    for (int it = 0; it < 4; it++) {
        int g = it * 256 + tid;
        int gg = g & 255;
        int row = gg >> 2, c8 = gg & 3;
        if (g < 256) {
            cp_async16(&sm->u.t.Ah[st][row][c8 * 8],
                       Xh4 + (size_t)(m0 + row) * 128 + kc4 + c8);
        } else if (g < 512) {
            cp_async16(&sm->u.t.Al[st][row][c8 * 8],
                       Xl4 + (size_t)(m0 + row) * 128 + kc4 + c8);
        } else if (g < 768) {
            cp_async16(&sm->u.t.Bh[st][row][c8 * 8],
                       Bh4 + (size_t)(n0 + row) * 128 + kc4 + c8);
        } else {
            cp_async16(&sm->u.t.Bl[st][row][c8 * 8],
                       Bl4 + (size_t)(n0 + row) * 128 + kc4 + c8);
        }
    }
}

__global__ __launch_bounds__(256) void gemm_wmma(
    const float* __restrict__ bias0, const float* __restrict__ bias1)
{
    extern __shared__ char dyn[];
    GemmSmemP* sm = reinterpret_cast<GemmSmemP*>(dyn);

    const int z  = blockIdx.z;
    const int n0 = blockIdx.x * 64;
    const int m0 = blockIdx.y * 64;
    const float* bias = z ? bias1 : bias0;

    const int tid = threadIdx.x;
    const int wid = tid >> 5;
    const int wr = wid & 3;
    const int wc = wid >> 2;

    const uint4* Xh4 = reinterpret_cast<const uint4*>(g_Xh);
    const uint4* Xl4 = reinterpret_cast<const uint4*>(g_Xl);
    const uint4* Bh4 = reinterpret_cast<const uint4*>(g_WhT) + (size_t)z * PADN * 128;
    const uint4* Bl4 = reinterpret_cast<const uint4*>(g_WlT) + (size_t)z * PADN * 128;

    wmma::fragment<wmma::accumulator, 16, 16, 16, float> c[2];
    wmma::fill_fragment(c[0], 0.f);
    wmma::fill_fragment(c[1], 0.f);

    gemm_prefetch(sm, 0, 0, m0, n0, tid, Xh4, Xl4, Bh4, Bl4);
    CP_COMMIT();

    for (int kc = 0; kc < 32; kc++) {
        const int cur = kc & 1;
        if (kc + 1 < 32) {
            gemm_prefetch(sm, cur ^ 1, kc + 1, m0, n0, tid, Xh4, Xl4, Bh4, Bl4);
            CP_COMMIT();
            CP_WAIT(1);
        } else {
            CP_WAIT(0);
        }
        __syncthreads();

        #pragma unroll
        for (int ks = 0; ks < 32; ks += 16) {
            wmma::fragment<wmma::matrix_a, 16, 16, 16, __nv_bfloat16, wmma::row_major> ah, al;
            wmma::fragment<wmma::matrix_b, 16, 16, 16, __nv_bfloat16, wmma::col_major> bh[2], bl[2];
            wmma::load_matrix_sync(ah, &sm->u.t.Ah[cur][wr * 16][ks], 40);
            wmma::load_matrix_sync(al, &sm->u.t.Al[cur][wr * 16][ks], 40);
            #pragma unroll
            for (int j = 0; j < 2; j++) {
                wmma::load_matrix_sync(bh[j], &sm->u.t.Bh[cur][wc * 32 + j * 16][ks], 40);
                wmma::load_matrix_sync(bl[j], &sm->u.t.Bl[cur][wc * 32 + j * 16][ks], 40);
            }
            #pragma unroll
            for (int j = 0; j < 2; j++) {
                wmma::mma_sync(c[j], ah, bh[j], c[j]);
                wmma::mma_sync(c[j], ah, bl[j], c[j]);
                wmma::mma_sync(c[j], al, bh[j], c[j]);
            }
        }
        __syncthreads();
    }

    #pragma unroll
    for (int j = 0; j < 2; j++)
        wmma::store_matrix_sync(&sm->u.out[wr * 16][wc * 32 + j * 16],
                                c[j], 68, wmma::mem_row_major);
    __syncthreads();

    __nv_bfloat16* dh = z ? g_kh : g_qh;
    __nv_bfloat16* dl = z ? g_kl : g_ql;
    float* conj_dst   = z ? g_conj_e : g_conj_s;

    for (int idx = tid; idx < 64 * 32; idx += 256) {
        int row = idx >> 5, cp = idx & 31;
        int n = n0 + cp * 2;
        if (n < TOT) {
            int e = n / DD, d = n - e * DD;
            int m = m0 + row;
            int b = m >> 9, l = m & 511;
            float v0 = sm->u.out[row][cp * 2]     + bias[n];
            float v1 = sm->u.out[row][cp * 2 + 1] + bias[n + 1];
            if (e < ENT) {
                int t = d >> 1;
                float cc = g_tcos[l * (DD / 2) + t];
                float ss = g_tsin[l * (DD / 2) + t];
                float r0 = v0 * cc - v1 * ss;
                float r1 = v1 * cc + v0 * ss;
                __nv_bfloat16 h0 = __float2bfloat16(r0);
                __nv_bfloat16 h1 = __float2bfloat16(r1);
                __nv_bfloat16 l0 = __float2bfloat16(r0 - __bfloat162float(h0));
                __nv_bfloat16 l1 = __float2bfloat16(r1 - __bfloat162float(h1));
                size_t o = (((size_t)(b * ENT + e)) * LL + l) * 64 + d;
                *reinterpret_cast<__nv_bfloat162*>(&dh[o]) =
                    __nv_bfloat162(h0, h1);
                *reinterpret_cast<__nv_bfloat162*>(&dl[o]) =
                    __nv_bfloat162(l0, l1);
            } else {
                size_t o = ((size_t)b * LL + l) * DD + d;
                conj_dst[o]     = v0;
                conj_dst[o + 1] = v1;
            }
        }
    }
}

// ---------------------------------------------------------------------------
// conj_diag — warp per (b,i), shfl reduce (fp32 e=16 slice)
// ---------------------------------------------------------------------------
__global__ __launch_bounds__(256) void conj_kernel()
{
    int wg = blockIdx.x * 8 + (threadIdx.x >> 5);
    int lane = threadIdx.x & 31;
    if (wg >= BB * NMASK) return;
    int b = wg / NMASK, i = wg - b * NMASK;
    const float* a = g_conj_s + ((size_t)b * LL + i) * DD;
    const float* c = g_conj_e + ((size_t)b * LL + i + 1) * DD;
    float s = 0.f;
    if (lane < DD)      s  = a[lane] * c[lane];
    if (lane + 32 < DD) s += a[lane + 32] * c[lane + 32];
    #pragma unroll
    for (int o = 16; o > 0; o >>= 1)
        s += __shfl_xor_sync(0xFFFFFFFFu, s, o);
    if (lane == 0) g_cd[wg] = s * SCALE;
}

// ---------------------------------------------------------------------------
// mask_kernel v3 — row-per-block: block = (i, ks); per k-plane the block
// streams the full contiguous 2KB row mask[k][i][0..511] (float2/thread),
// __ldcs (evict-first, zero reuse). grid (512, 4), 256 threads.
// ---------------------------------------------------------------------------
__global__ __launch_bounds__(256) void mask_kernel(const float* __restrict__ mask)
{
    __shared__ float scd[BB * NMASK];
    const int tid = threadIdx.x;
    for (int k = tid; k < BB * NMASK; k += 256) scd[k] = g_cd[k];

    const int i  = blockIdx.x;
    const int ks = blockIdx.y;
    const int j  = tid * 2;

    const int kbeg = ks * 128;
    const int kend = (ks == 3) ? NMASK : kbeg + 128;
    const float* mp = mask + (size_t)kbeg * (LL * LL) + (size_t)i * LL + j;

    __syncthreads();

    float2 a0 = make_float2(0.f, 0.f);
    float2 a1 = make_float2(0.f, 0.f);

    int k = kbeg;
    for (; k + 8 <= kend; k += 8) {
        float2 m[8];
        #pragma unroll
        for (int u = 0; u < 8; u++)
            m[u] = __ldcs(reinterpret_cast<const float2*>(
                       mp + (size_t)(k - kbeg + u) * (LL * LL)));
        #pragma unroll
        for (int u = 0; u < 8; u++) {
            float c0 = scd[k + u], c1 = scd[NMASK + k + u];
            a0.x = fmaf(c0, m[u].x, a0.x); a0.y = fmaf(c0, m[u].y, a0.y);
            a1.x = fmaf(c1, m[u].x, a1.x); a1.y = fmaf(c1, m[u].y, a1.y);
        }
    }
    for (; k < kend; k++) {
        float2 m = __ldcs(reinterpret_cast<const float2*>(
                       mp + (size_t)(k - kbeg) * (LL * LL)));
        float c0 = scd[k], c1 = scd[NMASK + k];
        a0.x = fmaf(c0, m.x, a0.x); a0.y = fmaf(c0, m.y, a0.y);
        a1.x = fmaf(c1, m.x, a1.x); a1.y = fmaf(c1, m.y, a1.y);
    }

    *reinterpret_cast<float2*>(&g_fm4[ks][0][(size_t)i * LL + j]) = a0;
    *reinterpret_cast<float2*>(&g_fm4[ks][1][(size_t)i * LL + j]) = a1;
}

// ---------------------------------------------------------------------------
// scores_wmma (R11 shape): (b, 32i x 32j) per block, split-bf16 WMMA.
// Epilogue sums the 4 k-split mask partials.
// ---------------------------------------------------------------------------
#define SS_LD   36
#define TILE_LD 72
#define SMEM_SS_BYTES   (16 * 32 * SS_LD * 4)
#define SMEM_TILE_BYTES (8 * 32 * TILE_LD * 2)
#define SCORES_SMEM     (SMEM_SS_BYTES + SMEM_TILE_BYTES)

__global__ __launch_bounds__(256) void scores_wmma(float* __restrict__ out)
{
    extern __shared__ char smem[];
    float* sS = reinterpret_cast<float*>(smem);
    __nv_bfloat16* tiles = reinterpret_cast<__nv_bfloat16*>(smem + SMEM_SS_BYTES);

    const int tid = threadIdx.x;
    const int wid = tid >> 5;
    const int j0 = blockIdx.x * 32;
    const int i0 = blockIdx.y * 32;
    const int b  = blockIdx.z;

    const uint4* qh4 = reinterpret_cast<const uint4*>(g_qh);
    const uint4* ql4 = reinterpret_cast<const uint4*>(g_ql);
    const uint4* kh4 = reinterpret_cast<const uint4*>(g_kh);
    const uint4* kl4 = reinterpret_cast<const uint4*>(g_kl);

    for (int ep = 0; ep < 8; ep++) {
        const int e0 = ep * 2;
        __syncthreads();
        #pragma unroll
        for (int it = 0; it < 8; it++) {
            int g = it * 256 + tid;
            int c   = g & 7;
            int r   = (g >> 3) & 31;
            int mat = g >> 8;
            int hl = mat & 1, el = (mat >> 1) & 1, qk = mat >> 2;
            const uint4* src = qk ? (hl ? kl4 : kh4) : (hl ? ql4 : qh4);
            int row0 = qk ? j0 : i0;
            size_t gi = ((size_t)(b * ENT + e0 + el) * LL + row0 + r) * 8 + c;
            uint4 v = src[gi];
            *reinterpret_cast<uint4*>(
                &tiles[((qk * 4 + el * 2 + hl) * 32 + r) * TILE_LD + c * 8]) = v;
        }
        __syncthreads();

        const int el  = wid >> 2;
        const int qi  = ((wid >> 1) & 1) * 16;
        const int qj  = (wid & 1) * 16;
        const __nv_bfloat16* Qh_ = &tiles[((el * 2 + 0) * 32 + qi) * TILE_LD];
        const __nv_bfloat16* Ql_ = &tiles[((el * 2 + 1) * 32 + qi) * TILE_LD];
        const __nv_bfloat16* Kh_ = &tiles[((4 + el * 2 + 0) * 32 + qj) * TILE_LD];
        const __nv_bfloat16* Kl_ = &tiles[((4 + el * 2 + 1) * 32 + qj) * TILE_LD];

        wmma::fragment<wmma::accumulator, 16, 16, 16, float> acc;
        wmma::fill_fragment(acc, 0.f);
        #pragma unroll
        for (int ks = 0; ks < 64; ks += 16) {
            wmma::fragment<wmma::matrix_a, 16, 16, 16, __nv_bfloat16, wmma::row_major> ah, al;
            wmma::fragment<wmma::matrix_b, 16, 16, 16, __nv_bfloat16, wmma::col_major> bh, bl;
            wmma::load_matrix_sync(ah, Qh_ + ks, TILE_LD);
            wmma::load_matrix_sync(al, Ql_ + ks, TILE_LD);
            wmma::load_matrix_sync(bh, Kh_ + ks, TILE_LD);
            wmma::load_matrix_sync(bl, Kl_ + ks, TILE_LD);
            wmma::mma_sync(acc, ah, bh, acc);
            wmma::mma_sync(acc, ah, bl, acc);
            wmma::mma_sync(acc, al, bh, acc);
        }
        wmma::store_matrix_sync(&sS[(e0 + el) * 32 * SS_LD + qi * SS_LD + qj],
                                acc, SS_LD, wmma::mem_row_major);
    }
    __syncthreads();

    for (int v = 0; v < 4; v++) {
        int lin = v * 256 + tid;
        int jj = lin & 31, ii = lin >> 5;
        int i = i0 + ii, j = j0 + jj;
        size_t fidx = (size_t)i * LL + j;
        float fm = (g_fm4[0][b][fidx] + g_fm4[1][b][fidx]) +
                   (g_fm4[2][b][fidx] + g_fm4[3][b][fidx]);
        float* op = out + ((((size_t)b * LL + i) * LL + j) * ENT);
        const float* sp = &sS[ii * SS_LD + jj];
        #pragma unroll
        for (int q = 0; q < 4; q++) {
            float4 w;
            w.x = fmaf(sp[(4 * q + 0) * 32 * SS_LD], SCALE, fm);
            w.y = fmaf(sp[(4 * q + 1) * 32 * SS_LD], SCALE, fm);
            w.z = fmaf(sp[(4 * q + 2) * 32 * SS_LD], SCALE, fm);
            w.w = fmaf(sp[(4 * q + 3) * 32 * SS_LD], SCALE, fm);
            *reinterpret_cast<float4*>(op + 4 * q) = w;
        }
    }
}

// ---------------------------------------------------------------------------
extern "C" void kernel_launch(void* const* d_in, const int* in_sizes, int n_in,
                              void* d_out, int out_size)
{
    const float* X    = (const float*)d_in[0];
    const float* mask = (const float*)d_in[1];
    const float* Ws   = (const float*)d_in[2];
    const float* bs   = (const float*)d_in[3];
    const float* We   = (const float*)d_in[4];
    const float* be   = (const float*)d_in[5];
    float* out        = (float*)d_out;

    cudaFuncSetAttribute(scores_wmma,
        cudaFuncAttributeMaxDynamicSharedMemorySize, SCORES_SMEM);
    cudaFuncSetAttribute(gemm_wmma,
        cudaFuncAttributeMaxDynamicSharedMemorySize, GEMM_SMEM);

    split_x<<<(1024 * 1024 / 4 + 255) / 256, 256>>>(X);
    split_wT<<<dim3(PADN / 32, HIN / 32, 2), dim3(32, 32)>>>(Ws, We);
    trig_table<<<(LL * (DD / 2) + 255) / 256, 256>>>();
    pad_zero<<<(4 * BB * ENT * LL + 255) / 256, 256>>>();

    gemm_wmma<<<dim3(PADN / 64, 1024 / 64, 2), 256, GEMM_SMEM>>>(bs, be);

    conj_kernel<<<(BB * NMASK + 7) / 8, 256>>>();

    mask_kernel<<<dim3(LL, 4), 256>>>(mask);
    scores_wmma<<<dim3(LL / 32, LL / 32, 2), 256, SCORES_SMEM>>>(out);
}